// round 13
// baseline (speedup 1.0000x reference)
#include <cuda_runtime.h>
#include <cuda_bf16.h>
#include <cuda_fp16.h>
#include <cstdint>

// Problem constants
#define BB   8
#define QQ   1024
#define KK   1024
#define EMBED 2048
#define DOWN  512
#define HH    16
#define DHD   32    // down head dim
#define DH    128   // value head dim

typedef __nv_bfloat16 bf16;

// ---------------- device scratch (allocation-free rule) ----------------
// bf16 splits (q/k GEMM inputs — 3-product accuracy for logits)
__device__ bf16 s_qh[BB * QQ * DOWN],  s_ql[BB * QQ * DOWN];
__device__ bf16 s_kh[BB * KK * DOWN],  s_kl[BB * KK * DOWN];
__device__ bf16 w_qh[DOWN * DOWN],   w_ql[DOWN * DOWN];
__device__ bf16 w_kh[DOWN * DOWN],   w_kl[DOWN * DOWN];
// fp16 splits (v path)
__device__ __half f_vh[BB * KK * EMBED], f_vl[BB * KK * EMBED];
__device__ __half f_wv[EMBED * EMBED];
// projections: Q fp16 hi/lo, K fp16 single, V fp16 single
__device__ __half q16h[BB * QQ * DOWN], q16l[BB * QQ * DOWN];
__device__ __half k16[BB * KK * DOWN];
__device__ __half p_vf[BB * KK * EMBED];
// unnormalized attention weights (fp16)
__device__ __half g_u[(size_t)BB * HH * QQ * KK];   // 268 MB

// ---------------- helpers ----------------
__device__ __forceinline__ uint32_t smem_u32(const void* p) {
    uint32_t a;
    asm("{ .reg .u64 t; cvta.to.shared.u64 t, %1; cvt.u32.u64 %0, t; }"
        : "=r"(a) : "l"(p));
    return a;
}
__device__ __forceinline__ void ldmx4(uint32_t* r, uint32_t addr) {
    asm volatile("ldmatrix.sync.aligned.m8n8.x4.shared.b16 {%0,%1,%2,%3}, [%4];"
                 : "=r"(r[0]), "=r"(r[1]), "=r"(r[2]), "=r"(r[3]) : "r"(addr));
}
__device__ __forceinline__ void ldmx4t(uint32_t* r, uint32_t addr) {
    asm volatile("ldmatrix.sync.aligned.m8n8.x4.trans.shared.b16 {%0,%1,%2,%3}, [%4];"
                 : "=r"(r[0]), "=r"(r[1]), "=r"(r[2]), "=r"(r[3]) : "r"(addr));
}
__device__ __forceinline__ void mma16816(float* d, const uint32_t* a, const uint32_t* b) {
    asm volatile(
        "mma.sync.aligned.m16n8k16.row.col.f32.bf16.bf16.f32 "
        "{%0,%1,%2,%3}, {%4,%5,%6,%7}, {%8,%9}, {%0,%1,%2,%3};"
        : "+f"(d[0]), "+f"(d[1]), "+f"(d[2]), "+f"(d[3])
        : "r"(a[0]), "r"(a[1]), "r"(a[2]), "r"(a[3]), "r"(b[0]), "r"(b[1]));
}
__device__ __forceinline__ void mma16816h(float* d, const uint32_t* a, const uint32_t* b) {
    asm volatile(
        "mma.sync.aligned.m16n8k16.row.col.f32.f16.f16.f32 "
        "{%0,%1,%2,%3}, {%4,%5,%6,%7}, {%8,%9}, {%0,%1,%2,%3};"
        : "+f"(d[0]), "+f"(d[1]), "+f"(d[2]), "+f"(d[3])
        : "r"(a[0]), "r"(a[1]), "r"(a[2]), "r"(a[3]), "r"(b[0]), "r"(b[1]));
}
__device__ __forceinline__ uint32_t bfpack(float x0, float x1) {
    uint32_t r;
    asm("cvt.rn.bf16x2.f32 %0, %1, %2;" : "=r"(r) : "f"(x1), "f"(x0));
    return r;
}
__device__ __forceinline__ float bftrunc(float x) {
    return __bfloat162float(__float2bfloat16_rn(x));
}
__device__ __forceinline__ uint32_t hfpack(float x0, float x1) {
    __half h0 = __float2half_rn(x0), h1 = __float2half_rn(x1);
    return ((uint32_t)__half_as_ushort(h1) << 16) | (uint32_t)__half_as_ushort(h0);
}
__device__ __forceinline__ float htrunc(float x) {
    return __half2float(__float2half_rn(x));
}
// cp.async (Ampere-era, valid on sm_103)
__device__ __forceinline__ void cpa16(uint32_t saddr, const void* g) {
    asm volatile("cp.async.cg.shared.global [%0], [%1], 16;"
                 :: "r"(saddr), "l"(g) : "memory");
}
#define CP_COMMIT() asm volatile("cp.async.commit_group;" ::: "memory")
#define CP_WAIT(n)  asm volatile("cp.async.wait_group %0;" :: "n"(n) : "memory")

// ---------------- split fp32 -> bf16 hi/lo ----------------
__global__ void __launch_bounds__(256)
split_bf16(const float* __restrict__ x, bf16* __restrict__ hi,
           bf16* __restrict__ lo, int n4) {
    int i = blockIdx.x * 256 + threadIdx.x;
    if (i >= n4) return;
    float4 v = ((const float4*)x)[i];
    float hx = bftrunc(v.x), hy = bftrunc(v.y), hz = bftrunc(v.z), hw = bftrunc(v.w);
    ((uint2*)hi)[i] = make_uint2(bfpack(hx, hy), bfpack(hz, hw));
    ((uint2*)lo)[i] = make_uint2(bfpack(v.x - hx, v.y - hy), bfpack(v.z - hz, v.w - hw));
}

// ---------------- split fp32 -> fp16 hi/lo ----------------
__global__ void __launch_bounds__(256)
split_fp16(const float* __restrict__ x, __half* __restrict__ hi,
           __half* __restrict__ lo, int n4) {
    int i = blockIdx.x * 256 + threadIdx.x;
    if (i >= n4) return;
    float4 v = ((const float4*)x)[i];
    float hx = htrunc(v.x), hy = htrunc(v.y), hz = htrunc(v.z), hw = htrunc(v.w);
    ((uint2*)hi)[i] = make_uint2(hfpack(hx, hy), hfpack(hz, hw));
    ((uint2*)lo)[i] = make_uint2(hfpack(v.x - hx, v.y - hy), hfpack(v.z - hz, v.w - hw));
}

// ---------------- HMMA GEMM bf16 3-product (q/k projections) ----------------
// OUT==0: emit fp16 hi/lo pair (Q). OUT==1: emit fp16 single (K).
#define GT_A_HI 0u
#define GT_A_LO 10240u
#define GT_B_HI 20480u
#define GT_B_LO 30720u
#define GT_STAGE 40960u
#define GT_BYTES (2u * GT_STAGE)   // 81920

template <int OUT>
__global__ void __launch_bounds__(256, 2)
gemm_mma_b(const bf16* __restrict__ Ah, const bf16* __restrict__ Al,
           const bf16* __restrict__ Wh, const bf16* __restrict__ Wl,
           const float* __restrict__ bias,
           __half* __restrict__ Ch, __half* __restrict__ Cl,
           int M, int N, int K) {
    extern __shared__ char smem[];
    const uint32_t sb = smem_u32(smem);
    const int tid = threadIdx.x;
    const int warp = tid >> 5, lane = tid & 31;
    const int wm = warp >> 2, wn = warp & 3;
    const int warp_row = wm * 64, warp_col = wn * 32;
    const int m0 = blockIdx.y * 128, n0 = blockIdx.x * 128;

    const int fr0 = tid >> 2, fc0 = tid & 3;
    const int fr1 = (tid + 256) >> 2, fc1 = (tid + 256) & 3;
    const uint32_t fo0 = (uint32_t)(fr0 * 80 + fc0 * 16);
    const uint32_t fo1 = (uint32_t)(fr1 * 80 + fc1 * 16);

    float acc[4][4][4];
#pragma unroll
    for (int i = 0; i < 4; i++)
#pragma unroll
        for (int j = 0; j < 4; j++)
#pragma unroll
            for (int t = 0; t < 4; t++) acc[i][j][t] = 0.f;

    const uint32_t a_lane_off = (uint32_t)((lane & 15) * 80 + (lane >> 4) * 16);
    const uint32_t b_lane_off = (uint32_t)(((lane >> 4) * 8 + (lane & 7)) * 80 + ((lane >> 3) & 1) * 16);

    const int nk = K >> 5;

    {
        const uint32_t st = sb;
        cpa16(st + GT_A_HI + fo0, Ah + (size_t)(m0 + fr0) * K + fc0 * 8);
        cpa16(st + GT_A_HI + fo1, Ah + (size_t)(m0 + fr1) * K + fc1 * 8);
        cpa16(st + GT_A_LO + fo0, Al + (size_t)(m0 + fr0) * K + fc0 * 8);
        cpa16(st + GT_A_LO + fo1, Al + (size_t)(m0 + fr1) * K + fc1 * 8);
        cpa16(st + GT_B_HI + fo0, Wh + (size_t)(n0 + fr0) * K + fc0 * 8);
        cpa16(st + GT_B_HI + fo1, Wh + (size_t)(n0 + fr1) * K + fc1 * 8);
        cpa16(st + GT_B_LO + fo0, Wl + (size_t)(n0 + fr0) * K + fc0 * 8);
        cpa16(st + GT_B_LO + fo1, Wl + (size_t)(n0 + fr1) * K + fc1 * 8);
        CP_COMMIT();
    }

    for (int i = 0; i < nk; i++) {
        CP_WAIT(0);
        __syncthreads();

        if (i + 1 < nk) {
            const int kt = (i + 1) << 5;
            const uint32_t st = sb + (uint32_t)((i + 1) & 1) * GT_STAGE;
            cpa16(st + GT_A_HI + fo0, Ah + (size_t)(m0 + fr0) * K + kt + fc0 * 8);
            cpa16(st + GT_A_HI + fo1, Ah + (size_t)(m0 + fr1) * K + kt + fc1 * 8);
            cpa16(st + GT_A_LO + fo0, Al + (size_t)(m0 + fr0) * K + kt + fc0 * 8);
            cpa16(st + GT_A_LO + fo1, Al + (size_t)(m0 + fr1) * K + kt + fc1 * 8);
            cpa16(st + GT_B_HI + fo0, Wh + (size_t)(n0 + fr0) * K + kt + fc0 * 8);
            cpa16(st + GT_B_HI + fo1, Wh + (size_t)(n0 + fr1) * K + kt + fc1 * 8);
            cpa16(st + GT_B_LO + fo0, Wl + (size_t)(n0 + fr0) * K + kt + fc0 * 8);
            cpa16(st + GT_B_LO + fo1, Wl + (size_t)(n0 + fr1) * K + kt + fc1 * 8);
            CP_COMMIT();
        }

        const uint32_t cur = sb + (uint32_t)(i & 1) * GT_STAGE;
#pragma unroll
        for (int kc = 0; kc < 2; kc++) {
            const uint32_t kco = (uint32_t)(kc * 32);
            uint32_t aH[4][4], aL[4][4], bfr[2][4];
#pragma unroll
            for (int mt = 0; mt < 4; mt++)
                ldmx4(aH[mt], cur + GT_A_HI + (uint32_t)((warp_row + mt * 16) * 80) + kco + a_lane_off);
#pragma unroll
            for (int np = 0; np < 2; np++)
                ldmx4(bfr[np], cur + GT_B_HI + (uint32_t)((warp_col + np * 16) * 80) + kco + b_lane_off);
#pragma unroll
            for (int mt = 0; mt < 4; mt++)
#pragma unroll
                for (int nt = 0; nt < 4; nt++)
                    mma16816(acc[mt][nt], aH[mt], &bfr[nt >> 1][(nt & 1) * 2]);
#pragma unroll
            for (int mt = 0; mt < 4; mt++)
                ldmx4(aL[mt], cur + GT_A_LO + (uint32_t)((warp_row + mt * 16) * 80) + kco + a_lane_off);
#pragma unroll
            for (int mt = 0; mt < 4; mt++)
#pragma unroll
                for (int nt = 0; nt < 4; nt++)
                    mma16816(acc[mt][nt], aL[mt], &bfr[nt >> 1][(nt & 1) * 2]);
#pragma unroll
            for (int np = 0; np < 2; np++)
                ldmx4(bfr[np], cur + GT_B_LO + (uint32_t)((warp_col + np * 16) * 80) + kco + b_lane_off);
#pragma unroll
            for (int mt = 0; mt < 4; mt++)
#pragma unroll
                for (int nt = 0; nt < 4; nt++)
                    mma16816(acc[mt][nt], aH[mt], &bfr[nt >> 1][(nt & 1) * 2]);
        }
    }

    const int lr = lane >> 2, lc = (lane & 3) * 2;
#pragma unroll
    for (int nt = 0; nt < 4; nt++) {
        int col = n0 + warp_col + nt * 8 + lc;
        float2 bb = *(const float2*)(bias + col);
#pragma unroll
        for (int mt = 0; mt < 4; mt++) {
            int row0 = m0 + warp_row + mt * 16 + lr;
            float c0 = acc[mt][nt][0] + bb.x, c1 = acc[mt][nt][1] + bb.y;
            float c2 = acc[mt][nt][2] + bb.x, c3 = acc[mt][nt][3] + bb.y;
            if (OUT == 0) {
                float h0 = htrunc(c0), h1 = htrunc(c1);
                float h2 = htrunc(c2), h3 = htrunc(c3);
                *(uint32_t*)(Ch + (size_t)row0 * N + col) = hfpack(h0, h1);
                *(uint32_t*)(Cl + (size_t)row0 * N + col) = hfpack(c0 - h0, c1 - h1);
                *(uint32_t*)(Ch + (size_t)(row0 + 8) * N + col) = hfpack(h2, h3);
                *(uint32_t*)(Cl + (size_t)(row0 + 8) * N + col) = hfpack(c2 - h2, c3 - h3);
            } else {
                *(uint32_t*)(Ch + (size_t)row0 * N + col) = hfpack(c0, c1);
                *(uint32_t*)(Ch + (size_t)(row0 + 8) * N + col) = hfpack(c2, c3);
            }
        }
    }
}

// ---------------- HMMA GEMM fp16 2-product (v projection, fp16 output) ----------------
#define GH_A_HI 0u
#define GH_A_LO 10240u
#define GH_B_HI 20480u
#define GH_STAGE 30720u
#define GH_BYTES (2u * GH_STAGE)   // 61440

__global__ void __launch_bounds__(256, 2)
gemm_mma_h(const __half* __restrict__ Ah, const __half* __restrict__ Al,
           const __half* __restrict__ Wh,
           const float* __restrict__ bias,
           __half* __restrict__ Cv,
           int M, int N, int K) {
    extern __shared__ char smem[];
    const uint32_t sb = smem_u32(smem);
    const int tid = threadIdx.x;
    const int warp = tid >> 5, lane = tid & 31;
    const int wm = warp >> 2, wn = warp & 3;
    const int warp_row = wm * 64, warp_col = wn * 32;
    const int m0 = blockIdx.y * 128, n0 = blockIdx.x * 128;

    const int fr0 = tid >> 2, fc0 = tid & 3;
    const int fr1 = (tid + 256) >> 2, fc1 = (tid + 256) & 3;
    const uint32_t fo0 = (uint32_t)(fr0 * 80 + fc0 * 16);
    const uint32_t fo1 = (uint32_t)(fr1 * 80 + fc1 * 16);

    float acc[4][4][4];
#pragma unroll
    for (int i = 0; i < 4; i++)
#pragma unroll
        for (int j = 0; j < 4; j++)
#pragma unroll
            for (int t = 0; t < 4; t++) acc[i][j][t] = 0.f;

    const uint32_t a_lane_off = (uint32_t)((lane & 15) * 80 + (lane >> 4) * 16);
    const uint32_t b_lane_off = (uint32_t)(((lane >> 4) * 8 + (lane & 7)) * 80 + ((lane >> 3) & 1) * 16);

    const int nk = K >> 5;

    {
        const uint32_t st = sb;
        cpa16(st + GH_A_HI + fo0, Ah + (size_t)(m0 + fr0) * K + fc0 * 8);
        cpa16(st + GH_A_HI + fo1, Ah + (size_t)(m0 + fr1) * K + fc1 * 8);
        cpa16(st + GH_A_LO + fo0, Al + (size_t)(m0 + fr0) * K + fc0 * 8);
        cpa16(st + GH_A_LO + fo1, Al + (size_t)(m0 + fr1) * K + fc1 * 8);
        cpa16(st + GH_B_HI + fo0, Wh + (size_t)(n0 + fr0) * K + fc0 * 8);
        cpa16(st + GH_B_HI + fo1, Wh + (size_t)(n0 + fr1) * K + fc1 * 8);
        CP_COMMIT();
    }

    for (int i = 0; i < nk; i++) {
        CP_WAIT(0);
        __syncthreads();

        if (i + 1 < nk) {
            const int kt = (i + 1) << 5;
            const uint32_t st = sb + (uint32_t)((i + 1) & 1) * GH_STAGE;
            cpa16(st + GH_A_HI + fo0, Ah + (size_t)(m0 + fr0) * K + kt + fc0 * 8);
            cpa16(st + GH_A_HI + fo1, Ah + (size_t)(m0 + fr1) * K + kt + fc1 * 8);
            cpa16(st + GH_A_LO + fo0, Al + (size_t)(m0 + fr0) * K + kt + fc0 * 8);
            cpa16(st + GH_A_LO + fo1, Al + (size_t)(m0 + fr1) * K + kt + fc1 * 8);
            cpa16(st + GH_B_HI + fo0, Wh + (size_t)(n0 + fr0) * K + kt + fc0 * 8);
            cpa16(st + GH_B_HI + fo1, Wh + (size_t)(n0 + fr1) * K + kt + fc1 * 8);
            CP_COMMIT();
        }

        const uint32_t cur = sb + (uint32_t)(i & 1) * GH_STAGE;
#pragma unroll
        for (int kc = 0; kc < 2; kc++) {
            const uint32_t kco = (uint32_t)(kc * 32);
            uint32_t aH[4][4], aL[4][4], bfr[2][4];
#pragma unroll
            for (int mt = 0; mt < 4; mt++)
                ldmx4(aH[mt], cur + GH_A_HI + (uint32_t)((warp_row + mt * 16) * 80) + kco + a_lane_off);
#pragma unroll
            for (int np = 0; np < 2; np++)
                ldmx4(bfr[np], cur + GH_B_HI + (uint32_t)((warp_col + np * 16) * 80) + kco + b_lane_off);
#pragma unroll
            for (int mt = 0; mt < 4; mt++)
#pragma unroll
                for (int nt = 0; nt < 4; nt++)
                    mma16816h(acc[mt][nt], aH[mt], &bfr[nt >> 1][(nt & 1) * 2]);
#pragma unroll
            for (int mt = 0; mt < 4; mt++)
                ldmx4(aL[mt], cur + GH_A_LO + (uint32_t)((warp_row + mt * 16) * 80) + kco + a_lane_off);
#pragma unroll
            for (int mt = 0; mt < 4; mt++)
#pragma unroll
                for (int nt = 0; nt < 4; nt++)
                    mma16816h(acc[mt][nt], aL[mt], &bfr[nt >> 1][(nt & 1) * 2]);
        }
    }

    const int lr = lane >> 2, lc = (lane & 3) * 2;
#pragma unroll
    for (int nt = 0; nt < 4; nt++) {
        int col = n0 + warp_col + nt * 8 + lc;
        float2 bb = *(const float2*)(bias + col);
#pragma unroll
        for (int mt = 0; mt < 4; mt++) {
            int row0 = m0 + warp_row + mt * 16 + lr;
            *(uint32_t*)(Cv + (size_t)row0 * N + col) =
                hfpack(acc[mt][nt][0] + bb.x, acc[mt][nt][1] + bb.y);
            *(uint32_t*)(Cv + (size_t)(row0 + 8) * N + col) =
                hfpack(acc[mt][nt][2] + bb.x, acc[mt][nt][3] + bb.y);
        }
    }
}

// ---------------- FA2-style attention: fp16 S (2-prod) + fp16 PV + fp16 u ----------------
// grid (Q/128, H, B), 256 threads (8 warps), 1 CTA/SM (110.6 KB smem).
#define AQ_HI 0u
#define AQ_LO 10240u
#define ABUF0 20480u
#define OFF_K 0u
#define OFF_V 10240u
#define ABUF_SZ 45056u            // K 10240 | V 34816
#define A_BYTES (ABUF0 + 2u * ABUF_SZ)   // 110592

__global__ void __launch_bounds__(256)
attn_mma(const __half* __restrict__ qh, const __half* __restrict__ ql,
         const __half* __restrict__ kf, const __half* __restrict__ vf,
         const float* __restrict__ mask,
         float* __restrict__ outO, float* __restrict__ outW,
         __half* __restrict__ gu) {
    const int b = blockIdx.z, h = blockIdx.y;
    const int qb0 = blockIdx.x * 128;
    const int tid = threadIdx.x;
    const int warp = tid >> 5, lane = tid & 31;
    const int lr = lane >> 2, lq = lane & 3;
    extern __shared__ char smem[];
    const uint32_t sb = smem_u32(smem);

    const uint32_t a80  = (uint32_t)((lane & 15) * 80 + (lane >> 4) * 16);
    const uint32_t b80  = (uint32_t)(((lane >> 4) * 8 + (lane & 7)) * 80 + ((lane >> 3) & 1) * 16);
    const uint32_t v272 = (uint32_t)((lane & 15) * 272 + (lane >> 4) * 16);

    const __half* kfp = kf + (size_t)b * KK * DOWN + h * DHD;
    const __half* vfp = vf + (size_t)b * KK * EMBED + h * DH;

    // ---- load Q tile [128,32] fp16 hi/lo ----
    {
        const __half* qhp = qh + (size_t)(b * QQ + qb0) * DOWN + h * DHD;
        const __half* qlp = ql + (size_t)(b * QQ + qb0) * DOWN + h * DHD;
#pragma unroll
        for (int l = 0; l < 2; l++) {
            int i = tid + l * 256;
            int r = i >> 2, c = i & 3;
            uint32_t off = (uint32_t)(r * 80 + c * 16);
            *(uint4*)(smem + AQ_HI + off) = *(const uint4*)(qhp + (size_t)r * DOWN + c * 8);
            *(uint4*)(smem + AQ_LO + off) = *(const uint4*)(qlp + (size_t)r * DOWN + c * 8);
        }
    }

    // ---- prologue: async-load chunk 0 into buffer 0 ----
    {
        const uint32_t bufb = sb + ABUF0;
#pragma unroll
        for (int l = 0; l < 2; l++) {
            int i = tid + l * 256;
            int r = i >> 2, c = i & 3;
            cpa16(bufb + OFF_K + (uint32_t)(r * 80 + c * 16),
                  kfp + (size_t)r * DOWN + c * 8);
        }
#pragma unroll
        for (int l = 0; l < 8; l++) {
            int i = tid + l * 256;
            int r = i >> 4, c = i & 15;
            cpa16(bufb + OFF_V + (uint32_t)(r * 272 + c * 16),
                  vfp + (size_t)r * EMBED + c * 8);
        }
        CP_COMMIT();
    }

    float oac[16][4];
#pragma unroll
    for (int i = 0; i < 16; i++)
#pragma unroll
        for (int t = 0; t < 4; t++) oac[i][t] = 0.f;
    float rs0 = 0.f, rs1 = 0.f;

    const float scale = 0.1767766952966369f; // 1/sqrt(32)
    const int rloc = warp * 16 + lr;
    const float* mbase = mask + (size_t)b * QQ * KK + (size_t)qb0 * KK;
    const size_t wb_off = ((size_t)((b * HH + h) * QQ + qb0)) * KK;
    __half* gub = gu + wb_off;

    for (int cc = 0; cc < 8; cc++) {
        const int kb2 = cc * 128;
        const uint32_t cur = sb + ABUF0 + (uint32_t)(cc & 1) * ABUF_SZ;

        CP_WAIT(0);
        __syncthreads();

        if (cc < 7) {
            const int kn = (cc + 1) * 128;
            const uint32_t nxt = sb + ABUF0 + (uint32_t)((cc + 1) & 1) * ABUF_SZ;
#pragma unroll
            for (int l = 0; l < 2; l++) {
                int i = tid + l * 256;
                int r = i >> 2, c = i & 3;
                cpa16(nxt + OFF_K + (uint32_t)(r * 80 + c * 16),
                      kfp + (size_t)(kn + r) * DOWN + c * 8);
            }
#pragma unroll
            for (int l = 0; l < 8; l++) {
                int i = tid + l * 256;
                int r = i >> 4, c = i & 15;
                cpa16(nxt + OFF_V + (uint32_t)(r * 272 + c * 16),
                      vfp + (size_t)(kn + r) * EMBED + c * 8);
            }
            CP_COMMIT();
        }

        // ---- S = Q*K^T (warp tile 16q x 128k), fp16 2-product ----
        float sac[16][4];
#pragma unroll
        for (int i = 0; i < 16; i++)
#pragma unroll
            for (int t = 0; t < 4; t++) sac[i][t] = 0.f;

#pragma unroll
        for (int kc = 0; kc < 2; kc++) {
            const uint32_t kco = (uint32_t)(kc * 32);
            uint32_t aH[4], aL[4];
            ldmx4(aH, sb + AQ_HI + (uint32_t)(warp * 16 * 80) + kco + a80);
            ldmx4(aL, sb + AQ_LO + (uint32_t)(warp * 16 * 80) + kco + a80);
#pragma unroll
            for (int np = 0; np < 8; np++) {
                uint32_t bf_[4];
                ldmx4(bf_, cur + OFF_K + (uint32_t)(np * 16 * 80) + kco + b80);
                mma16816h(sac[2 * np],     aH, bf_);
                mma16816h(sac[2 * np + 1], aH, bf_ + 2);
                mma16816h(sac[2 * np],     aL, bf_);
                mma16816h(sac[2 * np + 1], aL, bf_ + 2);
            }
        }

        // ---- exp + rowsum ----
#pragma unroll
        for (int nt = 0; nt < 16; nt++) {
            int col = kb2 + nt * 8 + 2 * lq;
            float2 ma = *(const float2*)(mbase + (size_t)rloc * KK + col);
            float2 mb = *(const float2*)(mbase + (size_t)(rloc + 8) * KK + col);
            float ta0 = (ma.x == 0.f) ? -10000.f : ma.x;
            float ta1 = (ma.y == 0.f) ? -10000.f : ma.y;
            float tb0 = (mb.x == 0.f) ? -10000.f : mb.x;
            float tb1 = (mb.y == 0.f) ? -10000.f : mb.y;
            float u0 = __expf(fmaf(sac[nt][0], scale, ta0));
            float u1 = __expf(fmaf(sac[nt][1], scale, ta1));
            float u2 = __expf(fmaf(sac[nt][2], scale, tb0));
            float u3 = __expf(fmaf(sac[nt][3], scale, tb1));
            rs0 += u0 + u1;
            rs1 += u2 + u3;
            sac[nt][0] = u0; sac[nt][1] = u1; sac[nt][2] = u2; sac[nt][3] = u3;
        }

        // ---- pack P (fp16 hi/lo), store hi to gu, PV 2-product ----
#pragma unroll
        for (int g = 0; g < 8; g++) {
            uint32_t phi[4], plo[4];
            {
                float u00 = sac[2 * g][0], u01 = sac[2 * g][1];
                float u02 = sac[2 * g][2], u03 = sac[2 * g][3];
                float u10 = sac[2 * g + 1][0], u11 = sac[2 * g + 1][1];
                float u12 = sac[2 * g + 1][2], u13 = sac[2 * g + 1][3];
                float h00 = htrunc(u00), h01 = htrunc(u01);
                float h02 = htrunc(u02), h03 = htrunc(u03);
                float h10 = htrunc(u10), h11 = htrunc(u11);
                float h12 = htrunc(u12), h13 = htrunc(u13);
                phi[0] = hfpack(h00, h01); plo[0] = hfpack(u00 - h00, u01 - h01);
                phi[1] = hfpack(h02, h03); plo[1] = hfpack(u02 - h02, u03 - h03);
                phi[2] = hfpack(h10, h11); plo[2] = hfpack(u10 - h10, u11 - h11);
                phi[3] = hfpack(h12, h13); plo[3] = hfpack(u12 - h12, u13 - h13);
            }
            // store unnormalized u (fp16 hi) — tail normalizes
            {
                int col = kb2 + g * 16 + 2 * lq;
                *(uint32_t*)(gub + (size_t)rloc * KK + col) = phi[0];
                *(uint32_t*)(gub + (size_t)(rloc + 8) * KK + col) = phi[1];
                *(uint32_t*)(gub + (size_t)rloc * KK + col + 8) = phi[2];
                *(uint32_t*)(gub + (size_t)(rloc + 8) * KK + col + 8) = phi[3];
            }
            const uint32_t grow = (uint32_t)(g * 16 * 272);
#pragma unroll
            for (int np = 0; np < 8; np++) {
                uint32_t vfr[4];
                ldmx4t(vfr, cur + OFF_V + grow + (uint32_t)(np * 32) + v272);
                mma16816h(oac[2 * np],     phi, vfr);
                mma16816h(oac[2 * np + 1], phi, vfr + 2);
                mma16816h(oac[2 * np],     plo, vfr);
                mma16816h(oac[2 * np + 1], plo, vfr + 2);
            }
        }
    }

    // ---- rowsum reduce within quad ----
    rs0 += __shfl_xor_sync(0xffffffffu, rs0, 1);
    rs0 += __shfl_xor_sync(0xffffffffu, rs0, 2);
    rs1 += __shfl_xor_sync(0xffffffffu, rs1, 1);
    rs1 += __shfl_xor_sync(0xffffffffu, rs1, 2);
    const float inv0 = 1.f / rs0;
    const float inv1 = 1.f / rs1;

    // ---- write O (normalized) ----
    {
        float* orow0 = outO + (size_t)(b * QQ + qb0 + rloc) * EMBED + h * DH;
        float* orow1 = outO + (size_t)(b * QQ + qb0 + rloc + 8) * EMBED + h * DH;
#pragma unroll
        for (int nt = 0; nt < 16; nt++) {
            int col = nt * 8 + 2 * lq;
            *(float2*)(orow0 + col) = make_float2(oac[nt][0] * inv0, oac[nt][1] * inv0);
            *(float2*)(orow1 + col) = make_float2(oac[nt][2] * inv1, oac[nt][3] * inv1);
        }
    }

    // ---- tail: read fp16 u, write normalized fp32 W ----
    {
        float* wbase = outW + wb_off;
        const __half* u0p = gub + (size_t)rloc * KK;
        const __half* u1p = gub + (size_t)(rloc + 8) * KK;
        float* wr0 = wbase + (size_t)rloc * KK;
        float* wr1 = wbase + (size_t)(rloc + 8) * KK;
        for (int c8 = lq * 8; c8 < KK; c8 += 32) {
            uint4 ua = *(const uint4*)(u0p + c8);
            __half2* ha = (__half2*)&ua;
            float2 f0 = __half22float2(ha[0]), f1 = __half22float2(ha[1]);
            float2 f2 = __half22float2(ha[2]), f3 = __half22float2(ha[3]);
            *(float4*)(wr0 + c8)     = make_float4(f0.x * inv0, f0.y * inv0, f1.x * inv0, f1.y * inv0);
            *(float4*)(wr0 + c8 + 4) = make_float4(f2.x * inv0, f2.y * inv0, f3.x * inv0, f3.y * inv0);
            uint4 ub = *(const uint4*)(u1p + c8);
            __half2* hb = (__half2*)&ub;
            f0 = __half22float2(hb[0]); f1 = __half22float2(hb[1]);
            f2 = __half22float2(hb[2]); f3 = __half22float2(hb[3]);
            *(float4*)(wr1 + c8)     = make_float4(f0.x * inv1, f0.y * inv1, f1.x * inv1, f1.y * inv1);
            *(float4*)(wr1 + c8 + 4) = make_float4(f2.x * inv1, f2.y * inv1, f3.x * inv1, f3.y * inv1);
        }
    }
}

// ---------------- launch ----------------
extern "C" void kernel_launch(void* const* d_in, const int* in_sizes, int n_in,
                              void* d_out, int out_size) {
    const float* query = (const float*)d_in[0];
    const float* key   = (const float*)d_in[1];
    const float* value = (const float*)d_in[2];
    const float* amask = (const float*)d_in[3];
    const float* qW = (const float*)d_in[4];
    const float* qb = (const float*)d_in[5];
    const float* kW = (const float*)d_in[6];
    const float* kb = (const float*)d_in[7];
    const float* vW = (const float*)d_in[8];
    const float* vb = (const float*)d_in[9];
    (void)in_sizes; (void)n_in; (void)out_size;

    float* outO = (float*)d_out;                             // [B,Q,EMBED]
    float* outW = outO + (size_t)BB * QQ * EMBED;            // [B,H,Q,K]

    bf16 *sqh, *sql, *skh, *skl;
    bf16 *wqh, *wql, *wkh, *wkl;
    __half *fvh, *fvl, *fwv, *pvf;
    __half *pqh, *pql, *pkf, *pgu;
    cudaGetSymbolAddress((void**)&sqh, s_qh); cudaGetSymbolAddress((void**)&sql, s_ql);
    cudaGetSymbolAddress((void**)&skh, s_kh); cudaGetSymbolAddress((void**)&skl, s_kl);
    cudaGetSymbolAddress((void**)&wqh, w_qh); cudaGetSymbolAddress((void**)&wql, w_ql);
    cudaGetSymbolAddress((void**)&wkh, w_kh); cudaGetSymbolAddress((void**)&wkl, w_kl);
    cudaGetSymbolAddress((void**)&fvh, f_vh); cudaGetSymbolAddress((void**)&fvl, f_vl);
    cudaGetSymbolAddress((void**)&fwv, f_wv); cudaGetSymbolAddress((void**)&pvf, p_vf);
    cudaGetSymbolAddress((void**)&pqh, q16h); cudaGetSymbolAddress((void**)&pql, q16l);
    cudaGetSymbolAddress((void**)&pkf, k16);  cudaGetSymbolAddress((void**)&pgu, g_u);

    // 1. splits
    {
        int n;
        n = BB * QQ * DOWN / 4;   split_bf16<<<(n + 255) / 256, 256>>>(query, sqh, sql, n);
        n = BB * KK * DOWN / 4;   split_bf16<<<(n + 255) / 256, 256>>>(key,   skh, skl, n);
        n = DOWN * DOWN / 4;      split_bf16<<<(n + 255) / 256, 256>>>(qW, wqh, wql, n);
        n = DOWN * DOWN / 4;      split_bf16<<<(n + 255) / 256, 256>>>(kW, wkh, wkl, n);
        n = BB * KK * EMBED / 4;  split_fp16<<<(n + 255) / 256, 256>>>(value, fvh, fvl, n);
        // vW: fp16 hi only; lo into q16l scratch (overwritten later by q GEMM)
        n = EMBED * EMBED / 4;
        split_fp16<<<(n + 255) / 256, 256>>>(vW, fwv, pql, n);
    }

    // 2. projection GEMMs
    {
        cudaFuncSetAttribute(gemm_mma_b<0>,
                             cudaFuncAttributeMaxDynamicSharedMemorySize, GT_BYTES);
        cudaFuncSetAttribute(gemm_mma_b<1>,
                             cudaFuncAttributeMaxDynamicSharedMemorySize, GT_BYTES);
        cudaFuncSetAttribute(gemm_mma_h,
                             cudaFuncAttributeMaxDynamicSharedMemorySize, GH_BYTES);
        dim3 gq(DOWN / 128, (BB * QQ) / 128);
        gemm_mma_b<0><<<gq, 256, GT_BYTES>>>(sqh, sql, wqh, wql, qb, pqh, pql,
                                             BB * QQ, DOWN, DOWN);
        gemm_mma_b<1><<<gq, 256, GT_BYTES>>>(skh, skl, wkh, wkl, kb, pkf, nullptr,
                                             BB * KK, DOWN, DOWN);
        dim3 gv(EMBED / 128, (BB * KK) / 128);
        gemm_mma_h<<<gv, 256, GH_BYTES>>>(fvh, fvl, fwv, vb, pvf,
                                          BB * KK, EMBED, EMBED);
    }

    // 3. attention (fp16 S 2-prod, fp16 PV 2-prod, fp16 u store, fused rescale)
    {
        cudaFuncSetAttribute(attn_mma,
                             cudaFuncAttributeMaxDynamicSharedMemorySize, A_BYTES);
        dim3 ga(QQ / 128, HH, BB);
        attn_mma<<<ga, 256, A_BYTES>>>(pqh, pql, pkf, pvf,
                                       amask, outO, outW, pgu);
    }
}

// round 14
// speedup vs baseline: 1.0702x; 1.0702x over previous
#include <cuda_runtime.h>
#include <cuda_bf16.h>
#include <cuda_fp16.h>
#include <cstdint>

// Problem constants
#define BB   8
#define QQ   1024
#define KK   1024
#define EMBED 2048
#define DOWN  512
#define HH    16
#define DHD   32    // down head dim
#define DH    128   // value head dim

typedef __nv_bfloat16 bf16;

// ---------------- device scratch (allocation-free rule) ----------------
// bf16 splits (q/k GEMM inputs — 3-product accuracy for logits)
__device__ bf16 s_qh[BB * QQ * DOWN],  s_ql[BB * QQ * DOWN];
__device__ bf16 s_kh[BB * KK * DOWN],  s_kl[BB * KK * DOWN];
__device__ bf16 w_qh[DOWN * DOWN],   w_ql[DOWN * DOWN];
__device__ bf16 w_kh[DOWN * DOWN],   w_kl[DOWN * DOWN];
// fp16 splits (v path)
__device__ __half f_vh[BB * KK * EMBED], f_vl[BB * KK * EMBED];
__device__ __half f_wv[EMBED * EMBED];
// projections: Q fp16 hi/lo, K fp16 single, V fp16 single
__device__ __half q16h[BB * QQ * DOWN], q16l[BB * QQ * DOWN];
__device__ __half k16[BB * KK * DOWN];
__device__ __half p_vf[BB * KK * EMBED];

// ---------------- helpers ----------------
__device__ __forceinline__ uint32_t smem_u32(const void* p) {
    uint32_t a;
    asm("{ .reg .u64 t; cvta.to.shared.u64 t, %1; cvt.u32.u64 %0, t; }"
        : "=r"(a) : "l"(p));
    return a;
}
__device__ __forceinline__ void ldmx4(uint32_t* r, uint32_t addr) {
    asm volatile("ldmatrix.sync.aligned.m8n8.x4.shared.b16 {%0,%1,%2,%3}, [%4];"
                 : "=r"(r[0]), "=r"(r[1]), "=r"(r[2]), "=r"(r[3]) : "r"(addr));
}
__device__ __forceinline__ void ldmx4t(uint32_t* r, uint32_t addr) {
    asm volatile("ldmatrix.sync.aligned.m8n8.x4.trans.shared.b16 {%0,%1,%2,%3}, [%4];"
                 : "=r"(r[0]), "=r"(r[1]), "=r"(r[2]), "=r"(r[3]) : "r"(addr));
}
__device__ __forceinline__ void mma16816(float* d, const uint32_t* a, const uint32_t* b) {
    asm volatile(
        "mma.sync.aligned.m16n8k16.row.col.f32.bf16.bf16.f32 "
        "{%0,%1,%2,%3}, {%4,%5,%6,%7}, {%8,%9}, {%0,%1,%2,%3};"
        : "+f"(d[0]), "+f"(d[1]), "+f"(d[2]), "+f"(d[3])
        : "r"(a[0]), "r"(a[1]), "r"(a[2]), "r"(a[3]), "r"(b[0]), "r"(b[1]));
}
__device__ __forceinline__ void mma16816h(float* d, const uint32_t* a, const uint32_t* b) {
    asm volatile(
        "mma.sync.aligned.m16n8k16.row.col.f32.f16.f16.f32 "
        "{%0,%1,%2,%3}, {%4,%5,%6,%7}, {%8,%9}, {%0,%1,%2,%3};"
        : "+f"(d[0]), "+f"(d[1]), "+f"(d[2]), "+f"(d[3])
        : "r"(a[0]), "r"(a[1]), "r"(a[2]), "r"(a[3]), "r"(b[0]), "r"(b[1]));
}
__device__ __forceinline__ uint32_t bfpack(float x0, float x1) {
    uint32_t r;
    asm("cvt.rn.bf16x2.f32 %0, %1, %2;" : "=r"(r) : "f"(x1), "f"(x0));
    return r;
}
__device__ __forceinline__ float bftrunc(float x) {
    return __bfloat162float(__float2bfloat16_rn(x));
}
__device__ __forceinline__ uint32_t hfpack(float x0, float x1) {
    __half h0 = __float2half_rn(x0), h1 = __float2half_rn(x1);
    return ((uint32_t)__half_as_ushort(h1) << 16) | (uint32_t)__half_as_ushort(h0);
}
__device__ __forceinline__ float htrunc(float x) {
    return __half2float(__float2half_rn(x));
}
// cp.async (Ampere-era, valid on sm_103)
__device__ __forceinline__ void cpa16(uint32_t saddr, const void* g) {
    asm volatile("cp.async.cg.shared.global [%0], [%1], 16;"
                 :: "r"(saddr), "l"(g) : "memory");
}
#define CP_COMMIT() asm volatile("cp.async.commit_group;" ::: "memory")
#define CP_WAIT(n)  asm volatile("cp.async.wait_group %0;" :: "n"(n) : "memory")

// ---------------- split fp32 -> bf16 hi/lo ----------------
__global__ void __launch_bounds__(256)
split_bf16(const float* __restrict__ x, bf16* __restrict__ hi,
           bf16* __restrict__ lo, int n4) {
    int i = blockIdx.x * 256 + threadIdx.x;
    if (i >= n4) return;
    float4 v = ((const float4*)x)[i];
    float hx = bftrunc(v.x), hy = bftrunc(v.y), hz = bftrunc(v.z), hw = bftrunc(v.w);
    ((uint2*)hi)[i] = make_uint2(bfpack(hx, hy), bfpack(hz, hw));
    ((uint2*)lo)[i] = make_uint2(bfpack(v.x - hx, v.y - hy), bfpack(v.z - hz, v.w - hw));
}

// ---------------- split fp32 -> fp16 hi/lo ----------------
__global__ void __launch_bounds__(256)
split_fp16(const float* __restrict__ x, __half* __restrict__ hi,
           __half* __restrict__ lo, int n4) {
    int i = blockIdx.x * 256 + threadIdx.x;
    if (i >= n4) return;
    float4 v = ((const float4*)x)[i];
    float hx = htrunc(v.x), hy = htrunc(v.y), hz = htrunc(v.z), hw = htrunc(v.w);
    ((uint2*)hi)[i] = make_uint2(hfpack(hx, hy), hfpack(hz, hw));
    ((uint2*)lo)[i] = make_uint2(hfpack(v.x - hx, v.y - hy), hfpack(v.z - hz, v.w - hw));
}

// ---------------- HMMA GEMM bf16 3-product (q/k projections) ----------------
// OUT==0: emit fp16 hi/lo pair (Q). OUT==1: emit fp16 single (K).
#define GT_A_HI 0u
#define GT_A_LO 10240u
#define GT_B_HI 20480u
#define GT_B_LO 30720u
#define GT_STAGE 40960u
#define GT_BYTES (2u * GT_STAGE)   // 81920

template <int OUT>
__global__ void __launch_bounds__(256, 2)
gemm_mma_b(const bf16* __restrict__ Ah, const bf16* __restrict__ Al,
           const bf16* __restrict__ Wh, const bf16* __restrict__ Wl,
           const float* __restrict__ bias,
           __half* __restrict__ Ch, __half* __restrict__ Cl,
           int M, int N, int K) {
    extern __shared__ char smem[];
    const uint32_t sb = smem_u32(smem);
    const int tid = threadIdx.x;
    const int warp = tid >> 5, lane = tid & 31;
    const int wm = warp >> 2, wn = warp & 3;
    const int warp_row = wm * 64, warp_col = wn * 32;
    const int m0 = blockIdx.y * 128, n0 = blockIdx.x * 128;

    const int fr0 = tid >> 2, fc0 = tid & 3;
    const int fr1 = (tid + 256) >> 2, fc1 = (tid + 256) & 3;
    const uint32_t fo0 = (uint32_t)(fr0 * 80 + fc0 * 16);
    const uint32_t fo1 = (uint32_t)(fr1 * 80 + fc1 * 16);

    float acc[4][4][4];
#pragma unroll
    for (int i = 0; i < 4; i++)
#pragma unroll
        for (int j = 0; j < 4; j++)
#pragma unroll
            for (int t = 0; t < 4; t++) acc[i][j][t] = 0.f;

    const uint32_t a_lane_off = (uint32_t)((lane & 15) * 80 + (lane >> 4) * 16);
    const uint32_t b_lane_off = (uint32_t)(((lane >> 4) * 8 + (lane & 7)) * 80 + ((lane >> 3) & 1) * 16);

    const int nk = K >> 5;

    {
        const uint32_t st = sb;
        cpa16(st + GT_A_HI + fo0, Ah + (size_t)(m0 + fr0) * K + fc0 * 8);
        cpa16(st + GT_A_HI + fo1, Ah + (size_t)(m0 + fr1) * K + fc1 * 8);
        cpa16(st + GT_A_LO + fo0, Al + (size_t)(m0 + fr0) * K + fc0 * 8);
        cpa16(st + GT_A_LO + fo1, Al + (size_t)(m0 + fr1) * K + fc1 * 8);
        cpa16(st + GT_B_HI + fo0, Wh + (size_t)(n0 + fr0) * K + fc0 * 8);
        cpa16(st + GT_B_HI + fo1, Wh + (size_t)(n0 + fr1) * K + fc1 * 8);
        cpa16(st + GT_B_LO + fo0, Wl + (size_t)(n0 + fr0) * K + fc0 * 8);
        cpa16(st + GT_B_LO + fo1, Wl + (size_t)(n0 + fr1) * K + fc1 * 8);
        CP_COMMIT();
    }

    for (int i = 0; i < nk; i++) {
        CP_WAIT(0);
        __syncthreads();

        if (i + 1 < nk) {
            const int kt = (i + 1) << 5;
            const uint32_t st = sb + (uint32_t)((i + 1) & 1) * GT_STAGE;
            cpa16(st + GT_A_HI + fo0, Ah + (size_t)(m0 + fr0) * K + kt + fc0 * 8);
            cpa16(st + GT_A_HI + fo1, Ah + (size_t)(m0 + fr1) * K + kt + fc1 * 8);
            cpa16(st + GT_A_LO + fo0, Al + (size_t)(m0 + fr0) * K + kt + fc0 * 8);
            cpa16(st + GT_A_LO + fo1, Al + (size_t)(m0 + fr1) * K + kt + fc1 * 8);
            cpa16(st + GT_B_HI + fo0, Wh + (size_t)(n0 + fr0) * K + kt + fc0 * 8);
            cpa16(st + GT_B_HI + fo1, Wh + (size_t)(n0 + fr1) * K + kt + fc1 * 8);
            cpa16(st + GT_B_LO + fo0, Wl + (size_t)(n0 + fr0) * K + kt + fc0 * 8);
            cpa16(st + GT_B_LO + fo1, Wl + (size_t)(n0 + fr1) * K + kt + fc1 * 8);
            CP_COMMIT();
        }

        const uint32_t cur = sb + (uint32_t)(i & 1) * GT_STAGE;
#pragma unroll
        for (int kc = 0; kc < 2; kc++) {
            const uint32_t kco = (uint32_t)(kc * 32);
            uint32_t aH[4][4], aL[4][4], bfr[2][4];
#pragma unroll
            for (int mt = 0; mt < 4; mt++)
                ldmx4(aH[mt], cur + GT_A_HI + (uint32_t)((warp_row + mt * 16) * 80) + kco + a_lane_off);
#pragma unroll
            for (int np = 0; np < 2; np++)
                ldmx4(bfr[np], cur + GT_B_HI + (uint32_t)((warp_col + np * 16) * 80) + kco + b_lane_off);
#pragma unroll
            for (int mt = 0; mt < 4; mt++)
#pragma unroll
                for (int nt = 0; nt < 4; nt++)
                    mma16816(acc[mt][nt], aH[mt], &bfr[nt >> 1][(nt & 1) * 2]);
#pragma unroll
            for (int mt = 0; mt < 4; mt++)
                ldmx4(aL[mt], cur + GT_A_LO + (uint32_t)((warp_row + mt * 16) * 80) + kco + a_lane_off);
#pragma unroll
            for (int mt = 0; mt < 4; mt++)
#pragma unroll
                for (int nt = 0; nt < 4; nt++)
                    mma16816(acc[mt][nt], aL[mt], &bfr[nt >> 1][(nt & 1) * 2]);
#pragma unroll
            for (int np = 0; np < 2; np++)
                ldmx4(bfr[np], cur + GT_B_LO + (uint32_t)((warp_col + np * 16) * 80) + kco + b_lane_off);
#pragma unroll
            for (int mt = 0; mt < 4; mt++)
#pragma unroll
                for (int nt = 0; nt < 4; nt++)
                    mma16816(acc[mt][nt], aH[mt], &bfr[nt >> 1][(nt & 1) * 2]);
        }
    }

    const int lr = lane >> 2, lc = (lane & 3) * 2;
#pragma unroll
    for (int nt = 0; nt < 4; nt++) {
        int col = n0 + warp_col + nt * 8 + lc;
        float2 bb = *(const float2*)(bias + col);
#pragma unroll
        for (int mt = 0; mt < 4; mt++) {
            int row0 = m0 + warp_row + mt * 16 + lr;
            float c0 = acc[mt][nt][0] + bb.x, c1 = acc[mt][nt][1] + bb.y;
            float c2 = acc[mt][nt][2] + bb.x, c3 = acc[mt][nt][3] + bb.y;
            if (OUT == 0) {
                float h0 = htrunc(c0), h1 = htrunc(c1);
                float h2 = htrunc(c2), h3 = htrunc(c3);
                *(uint32_t*)(Ch + (size_t)row0 * N + col) = hfpack(h0, h1);
                *(uint32_t*)(Cl + (size_t)row0 * N + col) = hfpack(c0 - h0, c1 - h1);
                *(uint32_t*)(Ch + (size_t)(row0 + 8) * N + col) = hfpack(h2, h3);
                *(uint32_t*)(Cl + (size_t)(row0 + 8) * N + col) = hfpack(c2 - h2, c3 - h3);
            } else {
                *(uint32_t*)(Ch + (size_t)row0 * N + col) = hfpack(c0, c1);
                *(uint32_t*)(Ch + (size_t)(row0 + 8) * N + col) = hfpack(c2, c3);
            }
        }
    }
}

// ---------------- HMMA GEMM fp16 2-product (v projection, fp16 output) ----------------
#define GH_A_HI 0u
#define GH_A_LO 10240u
#define GH_B_HI 20480u
#define GH_STAGE 30720u
#define GH_BYTES (2u * GH_STAGE)   // 61440

__global__ void __launch_bounds__(256, 2)
gemm_mma_h(const __half* __restrict__ Ah, const __half* __restrict__ Al,
           const __half* __restrict__ Wh,
           const float* __restrict__ bias,
           __half* __restrict__ Cv,
           int M, int N, int K) {
    extern __shared__ char smem[];
    const uint32_t sb = smem_u32(smem);
    const int tid = threadIdx.x;
    const int warp = tid >> 5, lane = tid & 31;
    const int wm = warp >> 2, wn = warp & 3;
    const int warp_row = wm * 64, warp_col = wn * 32;
    const int m0 = blockIdx.y * 128, n0 = blockIdx.x * 128;

    const int fr0 = tid >> 2, fc0 = tid & 3;
    const int fr1 = (tid + 256) >> 2, fc1 = (tid + 256) & 3;
    const uint32_t fo0 = (uint32_t)(fr0 * 80 + fc0 * 16);
    const uint32_t fo1 = (uint32_t)(fr1 * 80 + fc1 * 16);

    float acc[4][4][4];
#pragma unroll
    for (int i = 0; i < 4; i++)
#pragma unroll
        for (int j = 0; j < 4; j++)
#pragma unroll
            for (int t = 0; t < 4; t++) acc[i][j][t] = 0.f;

    const uint32_t a_lane_off = (uint32_t)((lane & 15) * 80 + (lane >> 4) * 16);
    const uint32_t b_lane_off = (uint32_t)(((lane >> 4) * 8 + (lane & 7)) * 80 + ((lane >> 3) & 1) * 16);

    const int nk = K >> 5;

    {
        const uint32_t st = sb;
        cpa16(st + GH_A_HI + fo0, Ah + (size_t)(m0 + fr0) * K + fc0 * 8);
        cpa16(st + GH_A_HI + fo1, Ah + (size_t)(m0 + fr1) * K + fc1 * 8);
        cpa16(st + GH_A_LO + fo0, Al + (size_t)(m0 + fr0) * K + fc0 * 8);
        cpa16(st + GH_A_LO + fo1, Al + (size_t)(m0 + fr1) * K + fc1 * 8);
        cpa16(st + GH_B_HI + fo0, Wh + (size_t)(n0 + fr0) * K + fc0 * 8);
        cpa16(st + GH_B_HI + fo1, Wh + (size_t)(n0 + fr1) * K + fc1 * 8);
        CP_COMMIT();
    }

    for (int i = 0; i < nk; i++) {
        CP_WAIT(0);
        __syncthreads();

        if (i + 1 < nk) {
            const int kt = (i + 1) << 5;
            const uint32_t st = sb + (uint32_t)((i + 1) & 1) * GH_STAGE;
            cpa16(st + GH_A_HI + fo0, Ah + (size_t)(m0 + fr0) * K + kt + fc0 * 8);
            cpa16(st + GH_A_HI + fo1, Ah + (size_t)(m0 + fr1) * K + kt + fc1 * 8);
            cpa16(st + GH_A_LO + fo0, Al + (size_t)(m0 + fr0) * K + kt + fc0 * 8);
            cpa16(st + GH_A_LO + fo1, Al + (size_t)(m0 + fr1) * K + kt + fc1 * 8);
            cpa16(st + GH_B_HI + fo0, Wh + (size_t)(n0 + fr0) * K + kt + fc0 * 8);
            cpa16(st + GH_B_HI + fo1, Wh + (size_t)(n0 + fr1) * K + kt + fc1 * 8);
            CP_COMMIT();
        }

        const uint32_t cur = sb + (uint32_t)(i & 1) * GH_STAGE;
#pragma unroll
        for (int kc = 0; kc < 2; kc++) {
            const uint32_t kco = (uint32_t)(kc * 32);
            uint32_t aH[4][4], aL[4][4], bfr[2][4];
#pragma unroll
            for (int mt = 0; mt < 4; mt++)
                ldmx4(aH[mt], cur + GH_A_HI + (uint32_t)((warp_row + mt * 16) * 80) + kco + a_lane_off);
#pragma unroll
            for (int np = 0; np < 2; np++)
                ldmx4(bfr[np], cur + GH_B_HI + (uint32_t)((warp_col + np * 16) * 80) + kco + b_lane_off);
#pragma unroll
            for (int mt = 0; mt < 4; mt++)
#pragma unroll
                for (int nt = 0; nt < 4; nt++)
                    mma16816h(acc[mt][nt], aH[mt], &bfr[nt >> 1][(nt & 1) * 2]);
#pragma unroll
            for (int mt = 0; mt < 4; mt++)
                ldmx4(aL[mt], cur + GH_A_LO + (uint32_t)((warp_row + mt * 16) * 80) + kco + a_lane_off);
#pragma unroll
            for (int mt = 0; mt < 4; mt++)
#pragma unroll
                for (int nt = 0; nt < 4; nt++)
                    mma16816h(acc[mt][nt], aL[mt], &bfr[nt >> 1][(nt & 1) * 2]);
        }
    }

    const int lr = lane >> 2, lc = (lane & 3) * 2;
#pragma unroll
    for (int nt = 0; nt < 4; nt++) {
        int col = n0 + warp_col + nt * 8 + lc;
        float2 bb = *(const float2*)(bias + col);
#pragma unroll
        for (int mt = 0; mt < 4; mt++) {
            int row0 = m0 + warp_row + mt * 16 + lr;
            *(uint32_t*)(Cv + (size_t)row0 * N + col) =
                hfpack(acc[mt][nt][0] + bb.x, acc[mt][nt][1] + bb.y);
            *(uint32_t*)(Cv + (size_t)(row0 + 8) * N + col) =
                hfpack(acc[mt][nt][2] + bb.x, acc[mt][nt][3] + bb.y);
        }
    }
}

// ---------------- FA2-style attention: fp16 S 2-prod, round-12 u handling ----------------
// grid (Q/128, H, B), 256 threads (8 warps), 1 CTA/SM (110.6 KB smem).
#define AQ_HI 0u
#define AQ_LO 10240u
#define ABUF0 20480u
#define OFF_K 0u
#define OFF_V 10240u
#define ABUF_SZ 45056u            // K 10240 | V 34816
#define A_BYTES (ABUF0 + 2u * ABUF_SZ)   // 110592

__global__ void __launch_bounds__(256)
attn_mma(const __half* __restrict__ qh, const __half* __restrict__ ql,
         const __half* __restrict__ kf, const __half* __restrict__ vf,
         const float* __restrict__ mask,
         float* __restrict__ outO, float* __restrict__ outW) {
    const int b = blockIdx.z, h = blockIdx.y;
    const int qb0 = blockIdx.x * 128;
    const int tid = threadIdx.x;
    const int warp = tid >> 5, lane = tid & 31;
    const int lr = lane >> 2, lq = lane & 3;
    extern __shared__ char smem[];
    const uint32_t sb = smem_u32(smem);

    const uint32_t a80  = (uint32_t)((lane & 15) * 80 + (lane >> 4) * 16);
    const uint32_t b80  = (uint32_t)(((lane >> 4) * 8 + (lane & 7)) * 80 + ((lane >> 3) & 1) * 16);
    const uint32_t v272 = (uint32_t)((lane & 15) * 272 + (lane >> 4) * 16);

    const __half* kfp = kf + (size_t)b * KK * DOWN + h * DHD;
    const __half* vfp = vf + (size_t)b * KK * EMBED + h * DH;

    // ---- load Q tile [128,32] fp16 hi/lo ----
    {
        const __half* qhp = qh + (size_t)(b * QQ + qb0) * DOWN + h * DHD;
        const __half* qlp = ql + (size_t)(b * QQ + qb0) * DOWN + h * DHD;
#pragma unroll
        for (int l = 0; l < 2; l++) {
            int i = tid + l * 256;
            int r = i >> 2, c = i & 3;
            uint32_t off = (uint32_t)(r * 80 + c * 16);
            *(uint4*)(smem + AQ_HI + off) = *(const uint4*)(qhp + (size_t)r * DOWN + c * 8);
            *(uint4*)(smem + AQ_LO + off) = *(const uint4*)(qlp + (size_t)r * DOWN + c * 8);
        }
    }

    // ---- prologue: async-load chunk 0 into buffer 0 ----
    {
        const uint32_t bufb = sb + ABUF0;
#pragma unroll
        for (int l = 0; l < 2; l++) {
            int i = tid + l * 256;
            int r = i >> 2, c = i & 3;
            cpa16(bufb + OFF_K + (uint32_t)(r * 80 + c * 16),
                  kfp + (size_t)r * DOWN + c * 8);
        }
#pragma unroll
        for (int l = 0; l < 8; l++) {
            int i = tid + l * 256;
            int r = i >> 4, c = i & 15;
            cpa16(bufb + OFF_V + (uint32_t)(r * 272 + c * 16),
                  vfp + (size_t)r * EMBED + c * 8);
        }
        CP_COMMIT();
    }

    float oac[16][4];
#pragma unroll
    for (int i = 0; i < 16; i++)
#pragma unroll
        for (int t = 0; t < 4; t++) oac[i][t] = 0.f;
    float rs0 = 0.f, rs1 = 0.f;

    const float scale = 0.1767766952966369f; // 1/sqrt(32)
    const int rloc = warp * 16 + lr;
    const float* mbase = mask + (size_t)b * QQ * KK + (size_t)qb0 * KK;
    float* wbase = outW + ((size_t)((b * HH + h) * QQ + qb0)) * KK;

    for (int cc = 0; cc < 8; cc++) {
        const int kb2 = cc * 128;
        const uint32_t cur = sb + ABUF0 + (uint32_t)(cc & 1) * ABUF_SZ;

        CP_WAIT(0);
        __syncthreads();

        if (cc < 7) {
            const int kn = (cc + 1) * 128;
            const uint32_t nxt = sb + ABUF0 + (uint32_t)((cc + 1) & 1) * ABUF_SZ;
#pragma unroll
            for (int l = 0; l < 2; l++) {
                int i = tid + l * 256;
                int r = i >> 2, c = i & 3;
                cpa16(nxt + OFF_K + (uint32_t)(r * 80 + c * 16),
                      kfp + (size_t)(kn + r) * DOWN + c * 8);
            }
#pragma unroll
            for (int l = 0; l < 8; l++) {
                int i = tid + l * 256;
                int r = i >> 4, c = i & 15;
                cpa16(nxt + OFF_V + (uint32_t)(r * 272 + c * 16),
                      vfp + (size_t)(kn + r) * EMBED + c * 8);
            }
            CP_COMMIT();
        }

        // ---- S = Q*K^T (warp tile 16q x 128k), fp16 2-product ----
        float sac[16][4];
#pragma unroll
        for (int i = 0; i < 16; i++)
#pragma unroll
            for (int t = 0; t < 4; t++) sac[i][t] = 0.f;

#pragma unroll
        for (int kc = 0; kc < 2; kc++) {
            const uint32_t kco = (uint32_t)(kc * 32);
            uint32_t aH[4], aL[4];
            ldmx4(aH, sb + AQ_HI + (uint32_t)(warp * 16 * 80) + kco + a80);
            ldmx4(aL, sb + AQ_LO + (uint32_t)(warp * 16 * 80) + kco + a80);
#pragma unroll
            for (int np = 0; np < 8; np++) {
                uint32_t bf_[4];
                ldmx4(bf_, cur + OFF_K + (uint32_t)(np * 16 * 80) + kco + b80);
                mma16816h(sac[2 * np],     aH, bf_);
                mma16816h(sac[2 * np + 1], aH, bf_ + 2);
                mma16816h(sac[2 * np],     aL, bf_);
                mma16816h(sac[2 * np + 1], aL, bf_ + 2);
            }
        }

        // ---- exp + rowsum + unnormalized fp32 u store to outW (round-12) ----
#pragma unroll
        for (int nt = 0; nt < 16; nt++) {
            int col = kb2 + nt * 8 + 2 * lq;
            float2 ma = *(const float2*)(mbase + (size_t)rloc * KK + col);
            float2 mb = *(const float2*)(mbase + (size_t)(rloc + 8) * KK + col);
            float ta0 = (ma.x == 0.f) ? -10000.f : ma.x;
            float ta1 = (ma.y == 0.f) ? -10000.f : ma.y;
            float tb0 = (mb.x == 0.f) ? -10000.f : mb.x;
            float tb1 = (mb.y == 0.f) ? -10000.f : mb.y;
            float u0 = __expf(fmaf(sac[nt][0], scale, ta0));
            float u1 = __expf(fmaf(sac[nt][1], scale, ta1));
            float u2 = __expf(fmaf(sac[nt][2], scale, tb0));
            float u3 = __expf(fmaf(sac[nt][3], scale, tb1));
            rs0 += u0 + u1;
            rs1 += u2 + u3;
            *(float2*)(wbase + (size_t)rloc * KK + col) = make_float2(u0, u1);
            *(float2*)(wbase + (size_t)(rloc + 8) * KK + col) = make_float2(u2, u3);
            sac[nt][0] = u0; sac[nt][1] = u1; sac[nt][2] = u2; sac[nt][3] = u3;
        }

        // ---- O += P @ V : fp16 register-P (hi/lo), fp16 V, 2 products ----
#pragma unroll
        for (int g = 0; g < 8; g++) {
            uint32_t phi[4], plo[4];
            {
                float u00 = sac[2 * g][0], u01 = sac[2 * g][1];
                float u02 = sac[2 * g][2], u03 = sac[2 * g][3];
                float u10 = sac[2 * g + 1][0], u11 = sac[2 * g + 1][1];
                float u12 = sac[2 * g + 1][2], u13 = sac[2 * g + 1][3];
                float h00 = htrunc(u00), h01 = htrunc(u01);
                float h02 = htrunc(u02), h03 = htrunc(u03);
                float h10 = htrunc(u10), h11 = htrunc(u11);
                float h12 = htrunc(u12), h13 = htrunc(u13);
                phi[0] = hfpack(h00, h01); plo[0] = hfpack(u00 - h00, u01 - h01);
                phi[1] = hfpack(h02, h03); plo[1] = hfpack(u02 - h02, u03 - h03);
                phi[2] = hfpack(h10, h11); plo[2] = hfpack(u10 - h10, u11 - h11);
                phi[3] = hfpack(h12, h13); plo[3] = hfpack(u12 - h12, u13 - h13);
            }
            const uint32_t grow = (uint32_t)(g * 16 * 272);
#pragma unroll
            for (int np = 0; np < 8; np++) {
                uint32_t vfr[4];
                ldmx4t(vfr, cur + OFF_V + grow + (uint32_t)(np * 32) + v272);
                mma16816h(oac[2 * np],     phi, vfr);
                mma16816h(oac[2 * np + 1], phi, vfr + 2);
                mma16816h(oac[2 * np],     plo, vfr);
                mma16816h(oac[2 * np + 1], plo, vfr + 2);
            }
        }
    }

    // ---- rowsum reduce within quad ----
    rs0 += __shfl_xor_sync(0xffffffffu, rs0, 1);
    rs0 += __shfl_xor_sync(0xffffffffu, rs0, 2);
    rs1 += __shfl_xor_sync(0xffffffffu, rs1, 1);
    rs1 += __shfl_xor_sync(0xffffffffu, rs1, 2);
    const float inv0 = 1.f / rs0;
    const float inv1 = 1.f / rs1;

    // ---- write O (normalized) ----
    {
        float* orow0 = outO + (size_t)(b * QQ + qb0 + rloc) * EMBED + h * DH;
        float* orow1 = outO + (size_t)(b * QQ + qb0 + rloc + 8) * EMBED + h * DH;
#pragma unroll
        for (int nt = 0; nt < 16; nt++) {
            int col = nt * 8 + 2 * lq;
            *(float2*)(orow0 + col) = make_float2(oac[nt][0] * inv0, oac[nt][1] * inv0);
            *(float2*)(orow1 + col) = make_float2(oac[nt][2] * inv1, oac[nt][3] * inv1);
        }
    }

    // ---- tail: rescale this warp's weight rows in place (round-12) ----
    {
        float* wr0 = wbase + (size_t)rloc * KK;
        float* wr1 = wbase + (size_t)(rloc + 8) * KK;
#pragma unroll 4
        for (int c4 = lq * 4; c4 < KK; c4 += 16) {
            float4 w0 = *(float4*)(wr0 + c4);
            w0.x *= inv0; w0.y *= inv0; w0.z *= inv0; w0.w *= inv0;
            *(float4*)(wr0 + c4) = w0;
            float4 w1 = *(float4*)(wr1 + c4);
            w1.x *= inv1; w1.y *= inv1; w1.z *= inv1; w1.w *= inv1;
            *(float4*)(wr1 + c4) = w1;
        }
    }
}

// ---------------- launch ----------------
extern "C" void kernel_launch(void* const* d_in, const int* in_sizes, int n_in,
                              void* d_out, int out_size) {
    const float* query = (const float*)d_in[0];
    const float* key   = (const float*)d_in[1];
    const float* value = (const float*)d_in[2];
    const float* amask = (const float*)d_in[3];
    const float* qW = (const float*)d_in[4];
    const float* qb = (const float*)d_in[5];
    const float* kW = (const float*)d_in[6];
    const float* kb = (const float*)d_in[7];
    const float* vW = (const float*)d_in[8];
    const float* vb = (const float*)d_in[9];
    (void)in_sizes; (void)n_in; (void)out_size;

    float* outO = (float*)d_out;                             // [B,Q,EMBED]
    float* outW = outO + (size_t)BB * QQ * EMBED;            // [B,H,Q,K]

    bf16 *sqh, *sql, *skh, *skl;
    bf16 *wqh, *wql, *wkh, *wkl;
    __half *fvh, *fvl, *fwv, *pvf;
    __half *pqh, *pql, *pkf;
    cudaGetSymbolAddress((void**)&sqh, s_qh); cudaGetSymbolAddress((void**)&sql, s_ql);
    cudaGetSymbolAddress((void**)&skh, s_kh); cudaGetSymbolAddress((void**)&skl, s_kl);
    cudaGetSymbolAddress((void**)&wqh, w_qh); cudaGetSymbolAddress((void**)&wql, w_ql);
    cudaGetSymbolAddress((void**)&wkh, w_kh); cudaGetSymbolAddress((void**)&wkl, w_kl);
    cudaGetSymbolAddress((void**)&fvh, f_vh); cudaGetSymbolAddress((void**)&fvl, f_vl);
    cudaGetSymbolAddress((void**)&fwv, f_wv); cudaGetSymbolAddress((void**)&pvf, p_vf);
    cudaGetSymbolAddress((void**)&pqh, q16h); cudaGetSymbolAddress((void**)&pql, q16l);
    cudaGetSymbolAddress((void**)&pkf, k16);

    // 1. splits
    {
        int n;
        n = BB * QQ * DOWN / 4;   split_bf16<<<(n + 255) / 256, 256>>>(query, sqh, sql, n);
        n = BB * KK * DOWN / 4;   split_bf16<<<(n + 255) / 256, 256>>>(key,   skh, skl, n);
        n = DOWN * DOWN / 4;      split_bf16<<<(n + 255) / 256, 256>>>(qW, wqh, wql, n);
        n = DOWN * DOWN / 4;      split_bf16<<<(n + 255) / 256, 256>>>(kW, wkh, wkl, n);
        n = BB * KK * EMBED / 4;  split_fp16<<<(n + 255) / 256, 256>>>(value, fvh, fvl, n);
        // vW: fp16 hi only; lo into q16l scratch (overwritten later by q GEMM)
        n = EMBED * EMBED / 4;
        split_fp16<<<(n + 255) / 256, 256>>>(vW, fwv, pql, n);
    }

    // 2. projection GEMMs
    {
        cudaFuncSetAttribute(gemm_mma_b<0>,
                             cudaFuncAttributeMaxDynamicSharedMemorySize, GT_BYTES);
        cudaFuncSetAttribute(gemm_mma_b<1>,
                             cudaFuncAttributeMaxDynamicSharedMemorySize, GT_BYTES);
        cudaFuncSetAttribute(gemm_mma_h,
                             cudaFuncAttributeMaxDynamicSharedMemorySize, GH_BYTES);
        dim3 gq(DOWN / 128, (BB * QQ) / 128);
        gemm_mma_b<0><<<gq, 256, GT_BYTES>>>(sqh, sql, wqh, wql, qb, pqh, pql,
                                             BB * QQ, DOWN, DOWN);
        gemm_mma_b<1><<<gq, 256, GT_BYTES>>>(skh, skl, wkh, wkl, kb, pkf, nullptr,
                                             BB * KK, DOWN, DOWN);
        dim3 gv(EMBED / 128, (BB * KK) / 128);
        gemm_mma_h<<<gv, 256, GH_BYTES>>>(fvh, fvl, fwv, vb, pvf,
                                          BB * KK, EMBED, EMBED);
    }

    // 3. attention (fp16 S 2-prod, fp16 PV 2-prod, round-12 u handling)
    {
        cudaFuncSetAttribute(attn_mma,
                             cudaFuncAttributeMaxDynamicSharedMemorySize, A_BYTES);
        dim3 ga(QQ / 128, HH, BB);
        attn_mma<<<ga, 256, A_BYTES>>>(pqh, pql, pkf, pvf,
                                       amask, outO, outW);
    }
}

// round 15
// speedup vs baseline: 1.3311x; 1.2437x over previous
#include <cuda_runtime.h>
#include <cuda_bf16.h>
#include <cuda_fp16.h>
#include <cstdint>

// Problem constants
#define BB   8
#define QQ   1024
#define KK   1024
#define EMBED 2048
#define DOWN  512
#define HH    16
#define DHD   32    // down head dim
#define DH    128   // value head dim

typedef __nv_bfloat16 bf16;

// ---------------- device scratch (allocation-free rule) ----------------
// bf16 splits (q/k GEMM inputs — 3-product accuracy for logits)
__device__ bf16 s_qh[BB * QQ * DOWN],  s_ql[BB * QQ * DOWN];
__device__ bf16 s_kh[BB * KK * DOWN],  s_kl[BB * KK * DOWN];
__device__ bf16 w_qh[DOWN * DOWN],   w_ql[DOWN * DOWN];
__device__ bf16 w_kh[DOWN * DOWN],   w_kl[DOWN * DOWN];
// fp16 singles (v path — O only)
__device__ __half f_v[BB * KK * EMBED];
__device__ __half f_wv[EMBED * EMBED];
// projections: Q fp16 hi/lo, K fp16 single, V fp16 single
__device__ __half q16h[BB * QQ * DOWN], q16l[BB * QQ * DOWN];
__device__ __half k16[BB * KK * DOWN];
__device__ __half p_vf[BB * KK * EMBED];

// ---------------- helpers ----------------
__device__ __forceinline__ uint32_t smem_u32(const void* p) {
    uint32_t a;
    asm("{ .reg .u64 t; cvta.to.shared.u64 t, %1; cvt.u32.u64 %0, t; }"
        : "=r"(a) : "l"(p));
    return a;
}
__device__ __forceinline__ void ldmx4(uint32_t* r, uint32_t addr) {
    asm volatile("ldmatrix.sync.aligned.m8n8.x4.shared.b16 {%0,%1,%2,%3}, [%4];"
                 : "=r"(r[0]), "=r"(r[1]), "=r"(r[2]), "=r"(r[3]) : "r"(addr));
}
__device__ __forceinline__ void ldmx4t(uint32_t* r, uint32_t addr) {
    asm volatile("ldmatrix.sync.aligned.m8n8.x4.trans.shared.b16 {%0,%1,%2,%3}, [%4];"
                 : "=r"(r[0]), "=r"(r[1]), "=r"(r[2]), "=r"(r[3]) : "r"(addr));
}
__device__ __forceinline__ void mma16816(float* d, const uint32_t* a, const uint32_t* b) {
    asm volatile(
        "mma.sync.aligned.m16n8k16.row.col.f32.bf16.bf16.f32 "
        "{%0,%1,%2,%3}, {%4,%5,%6,%7}, {%8,%9}, {%0,%1,%2,%3};"
        : "+f"(d[0]), "+f"(d[1]), "+f"(d[2]), "+f"(d[3])
        : "r"(a[0]), "r"(a[1]), "r"(a[2]), "r"(a[3]), "r"(b[0]), "r"(b[1]));
}
__device__ __forceinline__ void mma16816h(float* d, const uint32_t* a, const uint32_t* b) {
    asm volatile(
        "mma.sync.aligned.m16n8k16.row.col.f32.f16.f16.f32 "
        "{%0,%1,%2,%3}, {%4,%5,%6,%7}, {%8,%9}, {%0,%1,%2,%3};"
        : "+f"(d[0]), "+f"(d[1]), "+f"(d[2]), "+f"(d[3])
        : "r"(a[0]), "r"(a[1]), "r"(a[2]), "r"(a[3]), "r"(b[0]), "r"(b[1]));
}
__device__ __forceinline__ uint32_t bfpack(float x0, float x1) {
    uint32_t r;
    asm("cvt.rn.bf16x2.f32 %0, %1, %2;" : "=r"(r) : "f"(x1), "f"(x0));
    return r;
}
__device__ __forceinline__ float bftrunc(float x) {
    return __bfloat162float(__float2bfloat16_rn(x));
}
__device__ __forceinline__ uint32_t hfpack(float x0, float x1) {
    __half h0 = __float2half_rn(x0), h1 = __float2half_rn(x1);
    return ((uint32_t)__half_as_ushort(h1) << 16) | (uint32_t)__half_as_ushort(h0);
}
__device__ __forceinline__ float htrunc(float x) {
    return __half2float(__float2half_rn(x));
}
// cp.async (Ampere-era, valid on sm_103)
__device__ __forceinline__ void cpa16(uint32_t saddr, const void* g) {
    asm volatile("cp.async.cg.shared.global [%0], [%1], 16;"
                 :: "r"(saddr), "l"(g) : "memory");
}
#define CP_COMMIT() asm volatile("cp.async.commit_group;" ::: "memory")
#define CP_WAIT(n)  asm volatile("cp.async.wait_group %0;" :: "n"(n) : "memory")

// ---------------- split fp32 -> bf16 hi/lo ----------------
__global__ void __launch_bounds__(256)
split_bf16(const float* __restrict__ x, bf16* __restrict__ hi,
           bf16* __restrict__ lo, int n4) {
    int i = blockIdx.x * 256 + threadIdx.x;
    if (i >= n4) return;
    float4 v = ((const float4*)x)[i];
    float hx = bftrunc(v.x), hy = bftrunc(v.y), hz = bftrunc(v.z), hw = bftrunc(v.w);
    ((uint2*)hi)[i] = make_uint2(bfpack(hx, hy), bfpack(hz, hw));
    ((uint2*)lo)[i] = make_uint2(bfpack(v.x - hx, v.y - hy), bfpack(v.z - hz, v.w - hw));
}

// ---------------- convert fp32 -> fp16 (single) ----------------
__global__ void __launch_bounds__(256)
conv_fp16(const float* __restrict__ x, __half* __restrict__ y, int n4) {
    int i = blockIdx.x * 256 + threadIdx.x;
    if (i >= n4) return;
    float4 v = ((const float4*)x)[i];
    ((uint2*)y)[i] = make_uint2(hfpack(v.x, v.y), hfpack(v.z, v.w));
}

// ---------------- HMMA GEMM bf16 3-product (q/k projections) ----------------
// OUT==0: emit fp16 hi/lo pair (Q). OUT==1: emit fp16 single (K).
#define GT_A_HI 0u
#define GT_A_LO 10240u
#define GT_B_HI 20480u
#define GT_B_LO 30720u
#define GT_STAGE 40960u
#define GT_BYTES (2u * GT_STAGE)   // 81920

template <int OUT>
__global__ void __launch_bounds__(256, 2)
gemm_mma_b(const bf16* __restrict__ Ah, const bf16* __restrict__ Al,
           const bf16* __restrict__ Wh, const bf16* __restrict__ Wl,
           const float* __restrict__ bias,
           __half* __restrict__ Ch, __half* __restrict__ Cl,
           int M, int N, int K) {
    extern __shared__ char smem[];
    const uint32_t sb = smem_u32(smem);
    const int tid = threadIdx.x;
    const int warp = tid >> 5, lane = tid & 31;
    const int wm = warp >> 2, wn = warp & 3;
    const int warp_row = wm * 64, warp_col = wn * 32;
    const int m0 = blockIdx.y * 128, n0 = blockIdx.x * 128;

    const int fr0 = tid >> 2, fc0 = tid & 3;
    const int fr1 = (tid + 256) >> 2, fc1 = (tid + 256) & 3;
    const uint32_t fo0 = (uint32_t)(fr0 * 80 + fc0 * 16);
    const uint32_t fo1 = (uint32_t)(fr1 * 80 + fc1 * 16);

    float acc[4][4][4];
#pragma unroll
    for (int i = 0; i < 4; i++)
#pragma unroll
        for (int j = 0; j < 4; j++)
#pragma unroll
            for (int t = 0; t < 4; t++) acc[i][j][t] = 0.f;

    const uint32_t a_lane_off = (uint32_t)((lane & 15) * 80 + (lane >> 4) * 16);
    const uint32_t b_lane_off = (uint32_t)(((lane >> 4) * 8 + (lane & 7)) * 80 + ((lane >> 3) & 1) * 16);

    const int nk = K >> 5;

    {
        const uint32_t st = sb;
        cpa16(st + GT_A_HI + fo0, Ah + (size_t)(m0 + fr0) * K + fc0 * 8);
        cpa16(st + GT_A_HI + fo1, Ah + (size_t)(m0 + fr1) * K + fc1 * 8);
        cpa16(st + GT_A_LO + fo0, Al + (size_t)(m0 + fr0) * K + fc0 * 8);
        cpa16(st + GT_A_LO + fo1, Al + (size_t)(m0 + fr1) * K + fc1 * 8);
        cpa16(st + GT_B_HI + fo0, Wh + (size_t)(n0 + fr0) * K + fc0 * 8);
        cpa16(st + GT_B_HI + fo1, Wh + (size_t)(n0 + fr1) * K + fc1 * 8);
        cpa16(st + GT_B_LO + fo0, Wl + (size_t)(n0 + fr0) * K + fc0 * 8);
        cpa16(st + GT_B_LO + fo1, Wl + (size_t)(n0 + fr1) * K + fc1 * 8);
        CP_COMMIT();
    }

    for (int i = 0; i < nk; i++) {
        CP_WAIT(0);
        __syncthreads();

        if (i + 1 < nk) {
            const int kt = (i + 1) << 5;
            const uint32_t st = sb + (uint32_t)((i + 1) & 1) * GT_STAGE;
            cpa16(st + GT_A_HI + fo0, Ah + (size_t)(m0 + fr0) * K + kt + fc0 * 8);
            cpa16(st + GT_A_HI + fo1, Ah + (size_t)(m0 + fr1) * K + kt + fc1 * 8);
            cpa16(st + GT_A_LO + fo0, Al + (size_t)(m0 + fr0) * K + kt + fc0 * 8);
            cpa16(st + GT_A_LO + fo1, Al + (size_t)(m0 + fr1) * K + kt + fc1 * 8);
            cpa16(st + GT_B_HI + fo0, Wh + (size_t)(n0 + fr0) * K + kt + fc0 * 8);
            cpa16(st + GT_B_HI + fo1, Wh + (size_t)(n0 + fr1) * K + kt + fc1 * 8);
            cpa16(st + GT_B_LO + fo0, Wl + (size_t)(n0 + fr0) * K + kt + fc0 * 8);
            cpa16(st + GT_B_LO + fo1, Wl + (size_t)(n0 + fr1) * K + kt + fc1 * 8);
            CP_COMMIT();
        }

        const uint32_t cur = sb + (uint32_t)(i & 1) * GT_STAGE;
#pragma unroll
        for (int kc = 0; kc < 2; kc++) {
            const uint32_t kco = (uint32_t)(kc * 32);
            uint32_t aH[4][4], aL[4][4], bfr[2][4];
#pragma unroll
            for (int mt = 0; mt < 4; mt++)
                ldmx4(aH[mt], cur + GT_A_HI + (uint32_t)((warp_row + mt * 16) * 80) + kco + a_lane_off);
#pragma unroll
            for (int np = 0; np < 2; np++)
                ldmx4(bfr[np], cur + GT_B_HI + (uint32_t)((warp_col + np * 16) * 80) + kco + b_lane_off);
#pragma unroll
            for (int mt = 0; mt < 4; mt++)
#pragma unroll
                for (int nt = 0; nt < 4; nt++)
                    mma16816(acc[mt][nt], aH[mt], &bfr[nt >> 1][(nt & 1) * 2]);
#pragma unroll
            for (int mt = 0; mt < 4; mt++)
                ldmx4(aL[mt], cur + GT_A_LO + (uint32_t)((warp_row + mt * 16) * 80) + kco + a_lane_off);
#pragma unroll
            for (int mt = 0; mt < 4; mt++)
#pragma unroll
                for (int nt = 0; nt < 4; nt++)
                    mma16816(acc[mt][nt], aL[mt], &bfr[nt >> 1][(nt & 1) * 2]);
#pragma unroll
            for (int np = 0; np < 2; np++)
                ldmx4(bfr[np], cur + GT_B_LO + (uint32_t)((warp_col + np * 16) * 80) + kco + b_lane_off);
#pragma unroll
            for (int mt = 0; mt < 4; mt++)
#pragma unroll
                for (int nt = 0; nt < 4; nt++)
                    mma16816(acc[mt][nt], aH[mt], &bfr[nt >> 1][(nt & 1) * 2]);
        }
    }

    const int lr = lane >> 2, lc = (lane & 3) * 2;
#pragma unroll
    for (int nt = 0; nt < 4; nt++) {
        int col = n0 + warp_col + nt * 8 + lc;
        float2 bb = *(const float2*)(bias + col);
#pragma unroll
        for (int mt = 0; mt < 4; mt++) {
            int row0 = m0 + warp_row + mt * 16 + lr;
            float c0 = acc[mt][nt][0] + bb.x, c1 = acc[mt][nt][1] + bb.y;
            float c2 = acc[mt][nt][2] + bb.x, c3 = acc[mt][nt][3] + bb.y;
            if (OUT == 0) {
                float h0 = htrunc(c0), h1 = htrunc(c1);
                float h2 = htrunc(c2), h3 = htrunc(c3);
                *(uint32_t*)(Ch + (size_t)row0 * N + col) = hfpack(h0, h1);
                *(uint32_t*)(Cl + (size_t)row0 * N + col) = hfpack(c0 - h0, c1 - h1);
                *(uint32_t*)(Ch + (size_t)(row0 + 8) * N + col) = hfpack(h2, h3);
                *(uint32_t*)(Cl + (size_t)(row0 + 8) * N + col) = hfpack(c2 - h2, c3 - h3);
            } else {
                *(uint32_t*)(Ch + (size_t)row0 * N + col) = hfpack(c0, c1);
                *(uint32_t*)(Ch + (size_t)(row0 + 8) * N + col) = hfpack(c2, c3);
            }
        }
    }
}

// ---------------- HMMA GEMM fp16 single-product (v projection) ----------------
#define GH_A 0u
#define GH_B 10240u
#define GH_STAGE 20480u
#define GH_BYTES (2u * GH_STAGE)   // 40960

__global__ void __launch_bounds__(256, 2)
gemm_mma_h1(const __half* __restrict__ A, const __half* __restrict__ Wt,
            const float* __restrict__ bias,
            __half* __restrict__ Cv,
            int M, int N, int K) {
    extern __shared__ char smem[];
    const uint32_t sb = smem_u32(smem);
    const int tid = threadIdx.x;
    const int warp = tid >> 5, lane = tid & 31;
    const int wm = warp >> 2, wn = warp & 3;
    const int warp_row = wm * 64, warp_col = wn * 32;
    const int m0 = blockIdx.y * 128, n0 = blockIdx.x * 128;

    const int fr0 = tid >> 2, fc0 = tid & 3;
    const int fr1 = (tid + 256) >> 2, fc1 = (tid + 256) & 3;
    const uint32_t fo0 = (uint32_t)(fr0 * 80 + fc0 * 16);
    const uint32_t fo1 = (uint32_t)(fr1 * 80 + fc1 * 16);

    float acc[4][4][4];
#pragma unroll
    for (int i = 0; i < 4; i++)
#pragma unroll
        for (int j = 0; j < 4; j++)
#pragma unroll
            for (int t = 0; t < 4; t++) acc[i][j][t] = 0.f;

    const uint32_t a_lane_off = (uint32_t)((lane & 15) * 80 + (lane >> 4) * 16);
    const uint32_t b_lane_off = (uint32_t)(((lane >> 4) * 8 + (lane & 7)) * 80 + ((lane >> 3) & 1) * 16);

    const int nk = K >> 5;

    {
        const uint32_t st = sb;
        cpa16(st + GH_A + fo0, A + (size_t)(m0 + fr0) * K + fc0 * 8);
        cpa16(st + GH_A + fo1, A + (size_t)(m0 + fr1) * K + fc1 * 8);
        cpa16(st + GH_B + fo0, Wt + (size_t)(n0 + fr0) * K + fc0 * 8);
        cpa16(st + GH_B + fo1, Wt + (size_t)(n0 + fr1) * K + fc1 * 8);
        CP_COMMIT();
    }

    for (int i = 0; i < nk; i++) {
        CP_WAIT(0);
        __syncthreads();

        if (i + 1 < nk) {
            const int kt = (i + 1) << 5;
            const uint32_t st = sb + (uint32_t)((i + 1) & 1) * GH_STAGE;
            cpa16(st + GH_A + fo0, A + (size_t)(m0 + fr0) * K + kt + fc0 * 8);
            cpa16(st + GH_A + fo1, A + (size_t)(m0 + fr1) * K + kt + fc1 * 8);
            cpa16(st + GH_B + fo0, Wt + (size_t)(n0 + fr0) * K + kt + fc0 * 8);
            cpa16(st + GH_B + fo1, Wt + (size_t)(n0 + fr1) * K + kt + fc1 * 8);
            CP_COMMIT();
        }

        const uint32_t cur = sb + (uint32_t)(i & 1) * GH_STAGE;
#pragma unroll
        for (int kc = 0; kc < 2; kc++) {
            const uint32_t kco = (uint32_t)(kc * 32);
            uint32_t af[4][4], bfr[2][4];
#pragma unroll
            for (int mt = 0; mt < 4; mt++)
                ldmx4(af[mt], cur + GH_A + (uint32_t)((warp_row + mt * 16) * 80) + kco + a_lane_off);
#pragma unroll
            for (int np = 0; np < 2; np++)
                ldmx4(bfr[np], cur + GH_B + (uint32_t)((warp_col + np * 16) * 80) + kco + b_lane_off);
#pragma unroll
            for (int mt = 0; mt < 4; mt++)
#pragma unroll
                for (int nt = 0; nt < 4; nt++)
                    mma16816h(acc[mt][nt], af[mt], &bfr[nt >> 1][(nt & 1) * 2]);
        }
    }

    const int lr = lane >> 2, lc = (lane & 3) * 2;
#pragma unroll
    for (int nt = 0; nt < 4; nt++) {
        int col = n0 + warp_col + nt * 8 + lc;
        float2 bb = *(const float2*)(bias + col);
#pragma unroll
        for (int mt = 0; mt < 4; mt++) {
            int row0 = m0 + warp_row + mt * 16 + lr;
            *(uint32_t*)(Cv + (size_t)row0 * N + col) =
                hfpack(acc[mt][nt][0] + bb.x, acc[mt][nt][1] + bb.y);
            *(uint32_t*)(Cv + (size_t)(row0 + 8) * N + col) =
                hfpack(acc[mt][nt][2] + bb.x, acc[mt][nt][3] + bb.y);
        }
    }
}

// ---------------- FA2-style attention: fp16 S 2-prod, PV 1-prod ----------------
// grid (Q/128, H, B), 256 threads (8 warps), 1 CTA/SM (110.6 KB smem).
#define AQ_HI 0u
#define AQ_LO 10240u
#define ABUF0 20480u
#define OFF_K 0u
#define OFF_V 10240u
#define ABUF_SZ 45056u            // K 10240 | V 34816
#define A_BYTES (ABUF0 + 2u * ABUF_SZ)   // 110592

__global__ void __launch_bounds__(256)
attn_mma(const __half* __restrict__ qh, const __half* __restrict__ ql,
         const __half* __restrict__ kf, const __half* __restrict__ vf,
         const float* __restrict__ mask,
         float* __restrict__ outO, float* __restrict__ outW) {
    const int b = blockIdx.z, h = blockIdx.y;
    const int qb0 = blockIdx.x * 128;
    const int tid = threadIdx.x;
    const int warp = tid >> 5, lane = tid & 31;
    const int lr = lane >> 2, lq = lane & 3;
    extern __shared__ char smem[];
    const uint32_t sb = smem_u32(smem);

    const uint32_t a80  = (uint32_t)((lane & 15) * 80 + (lane >> 4) * 16);
    const uint32_t b80  = (uint32_t)(((lane >> 4) * 8 + (lane & 7)) * 80 + ((lane >> 3) & 1) * 16);
    const uint32_t v272 = (uint32_t)((lane & 15) * 272 + (lane >> 4) * 16);

    const __half* kfp = kf + (size_t)b * KK * DOWN + h * DHD;
    const __half* vfp = vf + (size_t)b * KK * EMBED + h * DH;

    // ---- load Q tile [128,32] fp16 hi/lo ----
    {
        const __half* qhp = qh + (size_t)(b * QQ + qb0) * DOWN + h * DHD;
        const __half* qlp = ql + (size_t)(b * QQ + qb0) * DOWN + h * DHD;
#pragma unroll
        for (int l = 0; l < 2; l++) {
            int i = tid + l * 256;
            int r = i >> 2, c = i & 3;
            uint32_t off = (uint32_t)(r * 80 + c * 16);
            *(uint4*)(smem + AQ_HI + off) = *(const uint4*)(qhp + (size_t)r * DOWN + c * 8);
            *(uint4*)(smem + AQ_LO + off) = *(const uint4*)(qlp + (size_t)r * DOWN + c * 8);
        }
    }

    // ---- prologue: async-load chunk 0 into buffer 0 ----
    {
        const uint32_t bufb = sb + ABUF0;
#pragma unroll
        for (int l = 0; l < 2; l++) {
            int i = tid + l * 256;
            int r = i >> 2, c = i & 3;
            cpa16(bufb + OFF_K + (uint32_t)(r * 80 + c * 16),
                  kfp + (size_t)r * DOWN + c * 8);
        }
#pragma unroll
        for (int l = 0; l < 8; l++) {
            int i = tid + l * 256;
            int r = i >> 4, c = i & 15;
            cpa16(bufb + OFF_V + (uint32_t)(r * 272 + c * 16),
                  vfp + (size_t)r * EMBED + c * 8);
        }
        CP_COMMIT();
    }

    float oac[16][4];
#pragma unroll
    for (int i = 0; i < 16; i++)
#pragma unroll
        for (int t = 0; t < 4; t++) oac[i][t] = 0.f;
    float rs0 = 0.f, rs1 = 0.f;

    const float scale = 0.1767766952966369f; // 1/sqrt(32)
    const int rloc = warp * 16 + lr;
    const float* mbase = mask + (size_t)b * QQ * KK + (size_t)qb0 * KK;
    float* wbase = outW + ((size_t)((b * HH + h) * QQ + qb0)) * KK;

    for (int cc = 0; cc < 8; cc++) {
        const int kb2 = cc * 128;
        const uint32_t cur = sb + ABUF0 + (uint32_t)(cc & 1) * ABUF_SZ;

        CP_WAIT(0);
        __syncthreads();

        if (cc < 7) {
            const int kn = (cc + 1) * 128;
            const uint32_t nxt = sb + ABUF0 + (uint32_t)((cc + 1) & 1) * ABUF_SZ;
#pragma unroll
            for (int l = 0; l < 2; l++) {
                int i = tid + l * 256;
                int r = i >> 2, c = i & 3;
                cpa16(nxt + OFF_K + (uint32_t)(r * 80 + c * 16),
                      kfp + (size_t)(kn + r) * DOWN + c * 8);
            }
#pragma unroll
            for (int l = 0; l < 8; l++) {
                int i = tid + l * 256;
                int r = i >> 4, c = i & 15;
                cpa16(nxt + OFF_V + (uint32_t)(r * 272 + c * 16),
                      vfp + (size_t)(kn + r) * EMBED + c * 8);
            }
            CP_COMMIT();
        }

        // ---- S = Q*K^T (warp tile 16q x 128k), fp16 2-product ----
        float sac[16][4];
#pragma unroll
        for (int i = 0; i < 16; i++)
#pragma unroll
            for (int t = 0; t < 4; t++) sac[i][t] = 0.f;

#pragma unroll
        for (int kc = 0; kc < 2; kc++) {
            const uint32_t kco = (uint32_t)(kc * 32);
            uint32_t aH[4], aL[4];
            ldmx4(aH, sb + AQ_HI + (uint32_t)(warp * 16 * 80) + kco + a80);
            ldmx4(aL, sb + AQ_LO + (uint32_t)(warp * 16 * 80) + kco + a80);
#pragma unroll
            for (int np = 0; np < 8; np++) {
                uint32_t bf_[4];
                ldmx4(bf_, cur + OFF_K + (uint32_t)(np * 16 * 80) + kco + b80);
                mma16816h(sac[2 * np],     aH, bf_);
                mma16816h(sac[2 * np + 1], aH, bf_ + 2);
                mma16816h(sac[2 * np],     aL, bf_);
                mma16816h(sac[2 * np + 1], aL, bf_ + 2);
            }
        }

        // ---- exp + rowsum + unnormalized fp32 u store to outW ----
#pragma unroll
        for (int nt = 0; nt < 16; nt++) {
            int col = kb2 + nt * 8 + 2 * lq;
            float2 ma = *(const float2*)(mbase + (size_t)rloc * KK + col);
            float2 mb = *(const float2*)(mbase + (size_t)(rloc + 8) * KK + col);
            float ta0 = (ma.x == 0.f) ? -10000.f : ma.x;
            float ta1 = (ma.y == 0.f) ? -10000.f : ma.y;
            float tb0 = (mb.x == 0.f) ? -10000.f : mb.x;
            float tb1 = (mb.y == 0.f) ? -10000.f : mb.y;
            float u0 = __expf(fmaf(sac[nt][0], scale, ta0));
            float u1 = __expf(fmaf(sac[nt][1], scale, ta1));
            float u2 = __expf(fmaf(sac[nt][2], scale, tb0));
            float u3 = __expf(fmaf(sac[nt][3], scale, tb1));
            rs0 += u0 + u1;
            rs1 += u2 + u3;
            *(float2*)(wbase + (size_t)rloc * KK + col) = make_float2(u0, u1);
            *(float2*)(wbase + (size_t)(rloc + 8) * KK + col) = make_float2(u2, u3);
            sac[nt][0] = u0; sac[nt][1] = u1; sac[nt][2] = u2; sac[nt][3] = u3;
        }

        // ---- O += P @ V : fp16 single-product (u quant 2^-11 — O path only) ----
#pragma unroll
        for (int g = 0; g < 8; g++) {
            uint32_t phi[4];
            phi[0] = hfpack(sac[2 * g][0],     sac[2 * g][1]);
            phi[1] = hfpack(sac[2 * g][2],     sac[2 * g][3]);
            phi[2] = hfpack(sac[2 * g + 1][0], sac[2 * g + 1][1]);
            phi[3] = hfpack(sac[2 * g + 1][2], sac[2 * g + 1][3]);
            const uint32_t grow = (uint32_t)(g * 16 * 272);
#pragma unroll
            for (int np = 0; np < 8; np++) {
                uint32_t vfr[4];
                ldmx4t(vfr, cur + OFF_V + grow + (uint32_t)(np * 32) + v272);
                mma16816h(oac[2 * np],     phi, vfr);
                mma16816h(oac[2 * np + 1], phi, vfr + 2);
            }
        }
    }

    // ---- rowsum reduce within quad ----
    rs0 += __shfl_xor_sync(0xffffffffu, rs0, 1);
    rs0 += __shfl_xor_sync(0xffffffffu, rs0, 2);
    rs1 += __shfl_xor_sync(0xffffffffu, rs1, 1);
    rs1 += __shfl_xor_sync(0xffffffffu, rs1, 2);
    const float inv0 = 1.f / rs0;
    const float inv1 = 1.f / rs1;

    // ---- write O (normalized) ----
    {
        float* orow0 = outO + (size_t)(b * QQ + qb0 + rloc) * EMBED + h * DH;
        float* orow1 = outO + (size_t)(b * QQ + qb0 + rloc + 8) * EMBED + h * DH;
#pragma unroll
        for (int nt = 0; nt < 16; nt++) {
            int col = nt * 8 + 2 * lq;
            *(float2*)(orow0 + col) = make_float2(oac[nt][0] * inv0, oac[nt][1] * inv0);
            *(float2*)(orow1 + col) = make_float2(oac[nt][2] * inv1, oac[nt][3] * inv1);
        }
    }

    // ---- tail: rescale this warp's weight rows in place ----
    {
        float* wr0 = wbase + (size_t)rloc * KK;
        float* wr1 = wbase + (size_t)(rloc + 8) * KK;
#pragma unroll 4
        for (int c4 = lq * 4; c4 < KK; c4 += 16) {
            float4 w0 = *(float4*)(wr0 + c4);
            w0.x *= inv0; w0.y *= inv0; w0.z *= inv0; w0.w *= inv0;
            *(float4*)(wr0 + c4) = w0;
            float4 w1 = *(float4*)(wr1 + c4);
            w1.x *= inv1; w1.y *= inv1; w1.z *= inv1; w1.w *= inv1;
            *(float4*)(wr1 + c4) = w1;
        }
    }
}

// ---------------- launch ----------------
extern "C" void kernel_launch(void* const* d_in, const int* in_sizes, int n_in,
                              void* d_out, int out_size) {
    const float* query = (const float*)d_in[0];
    const float* key   = (const float*)d_in[1];
    const float* value = (const float*)d_in[2];
    const float* amask = (const float*)d_in[3];
    const float* qW = (const float*)d_in[4];
    const float* qb = (const float*)d_in[5];
    const float* kW = (const float*)d_in[6];
    const float* kb = (const float*)d_in[7];
    const float* vW = (const float*)d_in[8];
    const float* vb = (const float*)d_in[9];
    (void)in_sizes; (void)n_in; (void)out_size;

    float* outO = (float*)d_out;                             // [B,Q,EMBED]
    float* outW = outO + (size_t)BB * QQ * EMBED;            // [B,H,Q,K]

    bf16 *sqh, *sql, *skh, *skl;
    bf16 *wqh, *wql, *wkh, *wkl;
    __half *fv, *fwv, *pvf;
    __half *pqh, *pql, *pkf;
    cudaGetSymbolAddress((void**)&sqh, s_qh); cudaGetSymbolAddress((void**)&sql, s_ql);
    cudaGetSymbolAddress((void**)&skh, s_kh); cudaGetSymbolAddress((void**)&skl, s_kl);
    cudaGetSymbolAddress((void**)&wqh, w_qh); cudaGetSymbolAddress((void**)&wql, w_ql);
    cudaGetSymbolAddress((void**)&wkh, w_kh); cudaGetSymbolAddress((void**)&wkl, w_kl);
    cudaGetSymbolAddress((void**)&fv, f_v);   cudaGetSymbolAddress((void**)&fwv, f_wv);
    cudaGetSymbolAddress((void**)&pvf, p_vf);
    cudaGetSymbolAddress((void**)&pqh, q16h); cudaGetSymbolAddress((void**)&pql, q16l);
    cudaGetSymbolAddress((void**)&pkf, k16);

    // 1. splits / converts
    {
        int n;
        n = BB * QQ * DOWN / 4;   split_bf16<<<(n + 255) / 256, 256>>>(query, sqh, sql, n);
        n = BB * KK * DOWN / 4;   split_bf16<<<(n + 255) / 256, 256>>>(key,   skh, skl, n);
        n = DOWN * DOWN / 4;      split_bf16<<<(n + 255) / 256, 256>>>(qW, wqh, wql, n);
        n = DOWN * DOWN / 4;      split_bf16<<<(n + 255) / 256, 256>>>(kW, wkh, wkl, n);
        n = BB * KK * EMBED / 4;  conv_fp16<<<(n + 255) / 256, 256>>>(value, fv, n);
        n = EMBED * EMBED / 4;    conv_fp16<<<(n + 255) / 256, 256>>>(vW, fwv, n);
    }

    // 2. projection GEMMs
    {
        cudaFuncSetAttribute(gemm_mma_b<0>,
                             cudaFuncAttributeMaxDynamicSharedMemorySize, GT_BYTES);
        cudaFuncSetAttribute(gemm_mma_b<1>,
                             cudaFuncAttributeMaxDynamicSharedMemorySize, GT_BYTES);
        cudaFuncSetAttribute(gemm_mma_h1,
                             cudaFuncAttributeMaxDynamicSharedMemorySize, GH_BYTES);
        dim3 gq(DOWN / 128, (BB * QQ) / 128);
        gemm_mma_b<0><<<gq, 256, GT_BYTES>>>(sqh, sql, wqh, wql, qb, pqh, pql,
                                             BB * QQ, DOWN, DOWN);
        gemm_mma_b<1><<<gq, 256, GT_BYTES>>>(skh, skl, wkh, wkl, kb, pkf, nullptr,
                                             BB * KK, DOWN, DOWN);
        dim3 gv(EMBED / 128, (BB * KK) / 128);
        gemm_mma_h1<<<gv, 256, GH_BYTES>>>(fv, fwv, vb, pvf,
                                           BB * KK, EMBED, EMBED);
    }

    // 3. attention (fp16 S 2-prod, PV 1-prod, fused rescale)
    {
        cudaFuncSetAttribute(attn_mma,
                             cudaFuncAttributeMaxDynamicSharedMemorySize, A_BYTES);
        dim3 ga(QQ / 128, HH, BB);
        attn_mma<<<ga, 256, A_BYTES>>>(pqh, pql, pkf, pvf,
                                       amask, outO, outW);
    }
}

// round 16
// speedup vs baseline: 1.3361x; 1.0038x over previous
#include <cuda_runtime.h>
#include <cuda_fp16.h>
#include <cstdint>

// Problem constants
#define BB   8
#define QQ   1024
#define KK   1024
#define EMBED 2048
#define DOWN  512
#define HH    16
#define DHD   32    // down head dim
#define DH    128   // value head dim

// ---------------- device scratch (allocation-free rule) ----------------
// fp16 hi/lo splits of inputs (exact to 2^-22), fp16 weights (2^-11 quant)
__device__ __half i_qh[BB * QQ * DOWN], i_ql[BB * QQ * DOWN];
__device__ __half i_kh[BB * KK * DOWN], i_kl[BB * KK * DOWN];
__device__ __half wq16[DOWN * DOWN], wk16[DOWN * DOWN];
__device__ __half f_v[BB * KK * EMBED];
__device__ __half f_wv[EMBED * EMBED];
// projections: Q fp16 hi/lo, K fp16 single, V fp16 single
__device__ __half q16h[BB * QQ * DOWN], q16l[BB * QQ * DOWN];
__device__ __half k16[BB * KK * DOWN];
__device__ __half p_vf[BB * KK * EMBED];

// ---------------- helpers ----------------
__device__ __forceinline__ uint32_t smem_u32(const void* p) {
    uint32_t a;
    asm("{ .reg .u64 t; cvta.to.shared.u64 t, %1; cvt.u32.u64 %0, t; }"
        : "=r"(a) : "l"(p));
    return a;
}
__device__ __forceinline__ void ldmx4(uint32_t* r, uint32_t addr) {
    asm volatile("ldmatrix.sync.aligned.m8n8.x4.shared.b16 {%0,%1,%2,%3}, [%4];"
                 : "=r"(r[0]), "=r"(r[1]), "=r"(r[2]), "=r"(r[3]) : "r"(addr));
}
__device__ __forceinline__ void ldmx4t(uint32_t* r, uint32_t addr) {
    asm volatile("ldmatrix.sync.aligned.m8n8.x4.trans.shared.b16 {%0,%1,%2,%3}, [%4];"
                 : "=r"(r[0]), "=r"(r[1]), "=r"(r[2]), "=r"(r[3]) : "r"(addr));
}
__device__ __forceinline__ void mma16816h(float* d, const uint32_t* a, const uint32_t* b) {
    asm volatile(
        "mma.sync.aligned.m16n8k16.row.col.f32.f16.f16.f32 "
        "{%0,%1,%2,%3}, {%4,%5,%6,%7}, {%8,%9}, {%0,%1,%2,%3};"
        : "+f"(d[0]), "+f"(d[1]), "+f"(d[2]), "+f"(d[3])
        : "r"(a[0]), "r"(a[1]), "r"(a[2]), "r"(a[3]), "r"(b[0]), "r"(b[1]));
}
__device__ __forceinline__ uint32_t hfpack(float x0, float x1) {
    __half h0 = __float2half_rn(x0), h1 = __float2half_rn(x1);
    return ((uint32_t)__half_as_ushort(h1) << 16) | (uint32_t)__half_as_ushort(h0);
}
__device__ __forceinline__ float htrunc(float x) {
    return __half2float(__float2half_rn(x));
}
// cp.async (Ampere-era, valid on sm_103)
__device__ __forceinline__ void cpa16(uint32_t saddr, const void* g) {
    asm volatile("cp.async.cg.shared.global [%0], [%1], 16;"
                 :: "r"(saddr), "l"(g) : "memory");
}
#define CP_COMMIT() asm volatile("cp.async.commit_group;" ::: "memory")
#define CP_WAIT(n)  asm volatile("cp.async.wait_group %0;" :: "n"(n) : "memory")

// ---------------- split fp32 -> fp16 hi/lo ----------------
__global__ void __launch_bounds__(256)
split_fp16(const float* __restrict__ x, __half* __restrict__ hi,
           __half* __restrict__ lo, int n4) {
    int i = blockIdx.x * 256 + threadIdx.x;
    if (i >= n4) return;
    float4 v = ((const float4*)x)[i];
    float hx = htrunc(v.x), hy = htrunc(v.y), hz = htrunc(v.z), hw = htrunc(v.w);
    ((uint2*)hi)[i] = make_uint2(hfpack(hx, hy), hfpack(hz, hw));
    ((uint2*)lo)[i] = make_uint2(hfpack(v.x - hx, v.y - hy), hfpack(v.z - hz, v.w - hw));
}

// ---------------- convert fp32 -> fp16 (single) ----------------
__global__ void __launch_bounds__(256)
conv_fp16(const float* __restrict__ x, __half* __restrict__ y, int n4) {
    int i = blockIdx.x * 256 + threadIdx.x;
    if (i >= n4) return;
    float4 v = ((const float4*)x)[i];
    ((uint2*)y)[i] = make_uint2(hfpack(v.x, v.y), hfpack(v.z, v.w));
}

// ---------------- fp16 2-product GEMM (q/k projections) ----------------
// C = (Ah + Al) @ Wf^T + bias.  OUT==0: emit fp16 hi/lo (Q). OUT==1: single (K).
#define GQ_A_HI 0u
#define GQ_A_LO 10240u
#define GQ_B    20480u
#define GQ_STAGE 30720u
#define GQ_BYTES (2u * GQ_STAGE)   // 61440

template <int OUT>
__global__ void __launch_bounds__(256, 2)
gemm_mma_q(const __half* __restrict__ Ah, const __half* __restrict__ Al,
           const __half* __restrict__ Wf,
           const float* __restrict__ bias,
           __half* __restrict__ Ch, __half* __restrict__ Cl,
           int M, int N, int K) {
    extern __shared__ char smem[];
    const uint32_t sb = smem_u32(smem);
    const int tid = threadIdx.x;
    const int warp = tid >> 5, lane = tid & 31;
    const int wm = warp >> 2, wn = warp & 3;
    const int warp_row = wm * 64, warp_col = wn * 32;
    const int m0 = blockIdx.y * 128, n0 = blockIdx.x * 128;

    const int fr0 = tid >> 2, fc0 = tid & 3;
    const int fr1 = (tid + 256) >> 2, fc1 = (tid + 256) & 3;
    const uint32_t fo0 = (uint32_t)(fr0 * 80 + fc0 * 16);
    const uint32_t fo1 = (uint32_t)(fr1 * 80 + fc1 * 16);

    float acc[4][4][4];
#pragma unroll
    for (int i = 0; i < 4; i++)
#pragma unroll
        for (int j = 0; j < 4; j++)
#pragma unroll
            for (int t = 0; t < 4; t++) acc[i][j][t] = 0.f;

    const uint32_t a_lane_off = (uint32_t)((lane & 15) * 80 + (lane >> 4) * 16);
    const uint32_t b_lane_off = (uint32_t)(((lane >> 4) * 8 + (lane & 7)) * 80 + ((lane >> 3) & 1) * 16);

    const int nk = K >> 5;

    {
        const uint32_t st = sb;
        cpa16(st + GQ_A_HI + fo0, Ah + (size_t)(m0 + fr0) * K + fc0 * 8);
        cpa16(st + GQ_A_HI + fo1, Ah + (size_t)(m0 + fr1) * K + fc1 * 8);
        cpa16(st + GQ_A_LO + fo0, Al + (size_t)(m0 + fr0) * K + fc0 * 8);
        cpa16(st + GQ_A_LO + fo1, Al + (size_t)(m0 + fr1) * K + fc1 * 8);
        cpa16(st + GQ_B + fo0, Wf + (size_t)(n0 + fr0) * K + fc0 * 8);
        cpa16(st + GQ_B + fo1, Wf + (size_t)(n0 + fr1) * K + fc1 * 8);
        CP_COMMIT();
    }

    for (int i = 0; i < nk; i++) {
        CP_WAIT(0);
        __syncthreads();

        if (i + 1 < nk) {
            const int kt = (i + 1) << 5;
            const uint32_t st = sb + (uint32_t)((i + 1) & 1) * GQ_STAGE;
            cpa16(st + GQ_A_HI + fo0, Ah + (size_t)(m0 + fr0) * K + kt + fc0 * 8);
            cpa16(st + GQ_A_HI + fo1, Ah + (size_t)(m0 + fr1) * K + kt + fc1 * 8);
            cpa16(st + GQ_A_LO + fo0, Al + (size_t)(m0 + fr0) * K + kt + fc0 * 8);
            cpa16(st + GQ_A_LO + fo1, Al + (size_t)(m0 + fr1) * K + kt + fc1 * 8);
            cpa16(st + GQ_B + fo0, Wf + (size_t)(n0 + fr0) * K + kt + fc0 * 8);
            cpa16(st + GQ_B + fo1, Wf + (size_t)(n0 + fr1) * K + kt + fc1 * 8);
            CP_COMMIT();
        }

        const uint32_t cur = sb + (uint32_t)(i & 1) * GQ_STAGE;
#pragma unroll
        for (int kc = 0; kc < 2; kc++) {
            const uint32_t kco = (uint32_t)(kc * 32);
            uint32_t aH[4][4], aL[4][4], bfr[2][4];
#pragma unroll
            for (int mt = 0; mt < 4; mt++)
                ldmx4(aH[mt], cur + GQ_A_HI + (uint32_t)((warp_row + mt * 16) * 80) + kco + a_lane_off);
#pragma unroll
            for (int np = 0; np < 2; np++)
                ldmx4(bfr[np], cur + GQ_B + (uint32_t)((warp_col + np * 16) * 80) + kco + b_lane_off);
#pragma unroll
            for (int mt = 0; mt < 4; mt++)
#pragma unroll
                for (int nt = 0; nt < 4; nt++)
                    mma16816h(acc[mt][nt], aH[mt], &bfr[nt >> 1][(nt & 1) * 2]);
#pragma unroll
            for (int mt = 0; mt < 4; mt++)
                ldmx4(aL[mt], cur + GQ_A_LO + (uint32_t)((warp_row + mt * 16) * 80) + kco + a_lane_off);
#pragma unroll
            for (int mt = 0; mt < 4; mt++)
#pragma unroll
                for (int nt = 0; nt < 4; nt++)
                    mma16816h(acc[mt][nt], aL[mt], &bfr[nt >> 1][(nt & 1) * 2]);
        }
    }

    const int lr = lane >> 2, lc = (lane & 3) * 2;
#pragma unroll
    for (int nt = 0; nt < 4; nt++) {
        int col = n0 + warp_col + nt * 8 + lc;
        float2 bb = *(const float2*)(bias + col);
#pragma unroll
        for (int mt = 0; mt < 4; mt++) {
            int row0 = m0 + warp_row + mt * 16 + lr;
            float c0 = acc[mt][nt][0] + bb.x, c1 = acc[mt][nt][1] + bb.y;
            float c2 = acc[mt][nt][2] + bb.x, c3 = acc[mt][nt][3] + bb.y;
            if (OUT == 0) {
                float h0 = htrunc(c0), h1 = htrunc(c1);
                float h2 = htrunc(c2), h3 = htrunc(c3);
                *(uint32_t*)(Ch + (size_t)row0 * N + col) = hfpack(h0, h1);
                *(uint32_t*)(Cl + (size_t)row0 * N + col) = hfpack(c0 - h0, c1 - h1);
                *(uint32_t*)(Ch + (size_t)(row0 + 8) * N + col) = hfpack(h2, h3);
                *(uint32_t*)(Cl + (size_t)(row0 + 8) * N + col) = hfpack(c2 - h2, c3 - h3);
            } else {
                *(uint32_t*)(Ch + (size_t)row0 * N + col) = hfpack(c0, c1);
                *(uint32_t*)(Ch + (size_t)(row0 + 8) * N + col) = hfpack(c2, c3);
            }
        }
    }
}

// ---------------- fp16 single-product GEMM (v projection) ----------------
#define GH_A 0u
#define GH_B 10240u
#define GH_STAGE 20480u
#define GH_BYTES (2u * GH_STAGE)   // 40960

__global__ void __launch_bounds__(256, 2)
gemm_mma_h1(const __half* __restrict__ A, const __half* __restrict__ Wt,
            const float* __restrict__ bias,
            __half* __restrict__ Cv,
            int M, int N, int K) {
    extern __shared__ char smem[];
    const uint32_t sb = smem_u32(smem);
    const int tid = threadIdx.x;
    const int warp = tid >> 5, lane = tid & 31;
    const int wm = warp >> 2, wn = warp & 3;
    const int warp_row = wm * 64, warp_col = wn * 32;
    const int m0 = blockIdx.y * 128, n0 = blockIdx.x * 128;

    const int fr0 = tid >> 2, fc0 = tid & 3;
    const int fr1 = (tid + 256) >> 2, fc1 = (tid + 256) & 3;
    const uint32_t fo0 = (uint32_t)(fr0 * 80 + fc0 * 16);
    const uint32_t fo1 = (uint32_t)(fr1 * 80 + fc1 * 16);

    float acc[4][4][4];
#pragma unroll
    for (int i = 0; i < 4; i++)
#pragma unroll
        for (int j = 0; j < 4; j++)
#pragma unroll
            for (int t = 0; t < 4; t++) acc[i][j][t] = 0.f;

    const uint32_t a_lane_off = (uint32_t)((lane & 15) * 80 + (lane >> 4) * 16);
    const uint32_t b_lane_off = (uint32_t)(((lane >> 4) * 8 + (lane & 7)) * 80 + ((lane >> 3) & 1) * 16);

    const int nk = K >> 5;

    {
        const uint32_t st = sb;
        cpa16(st + GH_A + fo0, A + (size_t)(m0 + fr0) * K + fc0 * 8);
        cpa16(st + GH_A + fo1, A + (size_t)(m0 + fr1) * K + fc1 * 8);
        cpa16(st + GH_B + fo0, Wt + (size_t)(n0 + fr0) * K + fc0 * 8);
        cpa16(st + GH_B + fo1, Wt + (size_t)(n0 + fr1) * K + fc1 * 8);
        CP_COMMIT();
    }

    for (int i = 0; i < nk; i++) {
        CP_WAIT(0);
        __syncthreads();

        if (i + 1 < nk) {
            const int kt = (i + 1) << 5;
            const uint32_t st = sb + (uint32_t)((i + 1) & 1) * GH_STAGE;
            cpa16(st + GH_A + fo0, A + (size_t)(m0 + fr0) * K + kt + fc0 * 8);
            cpa16(st + GH_A + fo1, A + (size_t)(m0 + fr1) * K + kt + fc1 * 8);
            cpa16(st + GH_B + fo0, Wt + (size_t)(n0 + fr0) * K + kt + fc0 * 8);
            cpa16(st + GH_B + fo1, Wt + (size_t)(n0 + fr1) * K + kt + fc1 * 8);
            CP_COMMIT();
        }

        const uint32_t cur = sb + (uint32_t)(i & 1) * GH_STAGE;
#pragma unroll
        for (int kc = 0; kc < 2; kc++) {
            const uint32_t kco = (uint32_t)(kc * 32);
            uint32_t af[4][4], bfr[2][4];
#pragma unroll
            for (int mt = 0; mt < 4; mt++)
                ldmx4(af[mt], cur + GH_A + (uint32_t)((warp_row + mt * 16) * 80) + kco + a_lane_off);
#pragma unroll
            for (int np = 0; np < 2; np++)
                ldmx4(bfr[np], cur + GH_B + (uint32_t)((warp_col + np * 16) * 80) + kco + b_lane_off);
#pragma unroll
            for (int mt = 0; mt < 4; mt++)
#pragma unroll
                for (int nt = 0; nt < 4; nt++)
                    mma16816h(acc[mt][nt], af[mt], &bfr[nt >> 1][(nt & 1) * 2]);
        }
    }

    const int lr = lane >> 2, lc = (lane & 3) * 2;
#pragma unroll
    for (int nt = 0; nt < 4; nt++) {
        int col = n0 + warp_col + nt * 8 + lc;
        float2 bb = *(const float2*)(bias + col);
#pragma unroll
        for (int mt = 0; mt < 4; mt++) {
            int row0 = m0 + warp_row + mt * 16 + lr;
            *(uint32_t*)(Cv + (size_t)row0 * N + col) =
                hfpack(acc[mt][nt][0] + bb.x, acc[mt][nt][1] + bb.y);
            *(uint32_t*)(Cv + (size_t)(row0 + 8) * N + col) =
                hfpack(acc[mt][nt][2] + bb.x, acc[mt][nt][3] + bb.y);
        }
    }
}

// ---------------- attention: fp16 S 2-prod, per-group fused exp+PV ----------------
// grid (Q/128, H, B), 256 threads (8 warps), 1 CTA/SM (110.6 KB smem).
#define AQ_HI 0u
#define AQ_LO 10240u
#define ABUF0 20480u
#define OFF_K 0u
#define OFF_V 10240u
#define ABUF_SZ 45056u            // K 10240 | V 34816
#define A_BYTES (ABUF0 + 2u * ABUF_SZ)   // 110592

__global__ void __launch_bounds__(256)
attn_mma(const __half* __restrict__ qh, const __half* __restrict__ ql,
         const __half* __restrict__ kf, const __half* __restrict__ vf,
         const float* __restrict__ mask,
         float* __restrict__ outO, float* __restrict__ outW) {
    const int b = blockIdx.z, h = blockIdx.y;
    const int qb0 = blockIdx.x * 128;
    const int tid = threadIdx.x;
    const int warp = tid >> 5, lane = tid & 31;
    const int lr = lane >> 2, lq = lane & 3;
    extern __shared__ char smem[];
    const uint32_t sb = smem_u32(smem);

    const uint32_t a80  = (uint32_t)((lane & 15) * 80 + (lane >> 4) * 16);
    const uint32_t b80  = (uint32_t)(((lane >> 4) * 8 + (lane & 7)) * 80 + ((lane >> 3) & 1) * 16);
    const uint32_t v272 = (uint32_t)((lane & 15) * 272 + (lane >> 4) * 16);

    const __half* kfp = kf + (size_t)b * KK * DOWN + h * DHD;
    const __half* vfp = vf + (size_t)b * KK * EMBED + h * DH;

    // ---- load Q tile [128,32] fp16 hi/lo ----
    {
        const __half* qhp = qh + (size_t)(b * QQ + qb0) * DOWN + h * DHD;
        const __half* qlp = ql + (size_t)(b * QQ + qb0) * DOWN + h * DHD;
#pragma unroll
        for (int l = 0; l < 2; l++) {
            int i = tid + l * 256;
            int r = i >> 2, c = i & 3;
            uint32_t off = (uint32_t)(r * 80 + c * 16);
            *(uint4*)(smem + AQ_HI + off) = *(const uint4*)(qhp + (size_t)r * DOWN + c * 8);
            *(uint4*)(smem + AQ_LO + off) = *(const uint4*)(qlp + (size_t)r * DOWN + c * 8);
        }
    }

    // ---- prologue: async-load chunk 0 into buffer 0 ----
    {
        const uint32_t bufb = sb + ABUF0;
#pragma unroll
        for (int l = 0; l < 2; l++) {
            int i = tid + l * 256;
            int r = i >> 2, c = i & 3;
            cpa16(bufb + OFF_K + (uint32_t)(r * 80 + c * 16),
                  kfp + (size_t)r * DOWN + c * 8);
        }
#pragma unroll
        for (int l = 0; l < 8; l++) {
            int i = tid + l * 256;
            int r = i >> 4, c = i & 15;
            cpa16(bufb + OFF_V + (uint32_t)(r * 272 + c * 16),
                  vfp + (size_t)r * EMBED + c * 8);
        }
        CP_COMMIT();
    }

    float oac[16][4];
#pragma unroll
    for (int i = 0; i < 16; i++)
#pragma unroll
        for (int t = 0; t < 4; t++) oac[i][t] = 0.f;
    float rs0 = 0.f, rs1 = 0.f;

    const float scale = 0.1767766952966369f; // 1/sqrt(32)
    const int rloc = warp * 16 + lr;
    const float* mbase = mask + (size_t)b * QQ * KK + (size_t)qb0 * KK;
    float* wbase = outW + ((size_t)((b * HH + h) * QQ + qb0)) * KK;

    for (int cc = 0; cc < 8; cc++) {
        const int kb2 = cc * 128;
        const uint32_t cur = sb + ABUF0 + (uint32_t)(cc & 1) * ABUF_SZ;

        CP_WAIT(0);
        __syncthreads();

        if (cc < 7) {
            const int kn = (cc + 1) * 128;
            const uint32_t nxt = sb + ABUF0 + (uint32_t)((cc + 1) & 1) * ABUF_SZ;
#pragma unroll
            for (int l = 0; l < 2; l++) {
                int i = tid + l * 256;
                int r = i >> 2, c = i & 3;
                cpa16(nxt + OFF_K + (uint32_t)(r * 80 + c * 16),
                      kfp + (size_t)(kn + r) * DOWN + c * 8);
            }
#pragma unroll
            for (int l = 0; l < 8; l++) {
                int i = tid + l * 256;
                int r = i >> 4, c = i & 15;
                cpa16(nxt + OFF_V + (uint32_t)(r * 272 + c * 16),
                      vfp + (size_t)(kn + r) * EMBED + c * 8);
            }
            CP_COMMIT();
        }

        // ---- S = Q*K^T (warp tile 16q x 128k), fp16 2-product ----
        float sac[16][4];
#pragma unroll
        for (int i = 0; i < 16; i++)
#pragma unroll
            for (int t = 0; t < 4; t++) sac[i][t] = 0.f;

#pragma unroll
        for (int kc = 0; kc < 2; kc++) {
            const uint32_t kco = (uint32_t)(kc * 32);
            uint32_t aH[4], aL[4];
            ldmx4(aH, sb + AQ_HI + (uint32_t)(warp * 16 * 80) + kco + a80);
            ldmx4(aL, sb + AQ_LO + (uint32_t)(warp * 16 * 80) + kco + a80);
#pragma unroll
            for (int np = 0; np < 8; np++) {
                uint32_t bf_[4];
                ldmx4(bf_, cur + OFF_K + (uint32_t)(np * 16 * 80) + kco + b80);
                mma16816h(sac[2 * np],     aH, bf_);
                mma16816h(sac[2 * np + 1], aH, bf_ + 2);
                mma16816h(sac[2 * np],     aL, bf_);
                mma16816h(sac[2 * np + 1], aL, bf_ + 2);
            }
        }

        // ---- per-group fused: exp + rowsum + W store + PV mma (MUFU/tensor overlap) ----
#pragma unroll
        for (int g = 0; g < 8; g++) {
            uint32_t phi[4];
#pragma unroll
            for (int j = 0; j < 2; j++) {
                const int nt = 2 * g + j;
                int col = kb2 + nt * 8 + 2 * lq;
                float2 ma = *(const float2*)(mbase + (size_t)rloc * KK + col);
                float2 mb = *(const float2*)(mbase + (size_t)(rloc + 8) * KK + col);
                float ta0 = (ma.x == 0.f) ? -10000.f : ma.x;
                float ta1 = (ma.y == 0.f) ? -10000.f : ma.y;
                float tb0 = (mb.x == 0.f) ? -10000.f : mb.x;
                float tb1 = (mb.y == 0.f) ? -10000.f : mb.y;
                float u0 = __expf(fmaf(sac[nt][0], scale, ta0));
                float u1 = __expf(fmaf(sac[nt][1], scale, ta1));
                float u2 = __expf(fmaf(sac[nt][2], scale, tb0));
                float u3 = __expf(fmaf(sac[nt][3], scale, tb1));
                rs0 += u0 + u1;
                rs1 += u2 + u3;
                *(float2*)(wbase + (size_t)rloc * KK + col) = make_float2(u0, u1);
                *(float2*)(wbase + (size_t)(rloc + 8) * KK + col) = make_float2(u2, u3);
                phi[2 * j]     = hfpack(u0, u1);
                phi[2 * j + 1] = hfpack(u2, u3);
            }
            const uint32_t grow = (uint32_t)(g * 16 * 272);
#pragma unroll
            for (int np = 0; np < 8; np++) {
                uint32_t vfr[4];
                ldmx4t(vfr, cur + OFF_V + grow + (uint32_t)(np * 32) + v272);
                mma16816h(oac[2 * np],     phi, vfr);
                mma16816h(oac[2 * np + 1], phi, vfr + 2);
            }
        }
    }

    // ---- rowsum reduce within quad ----
    rs0 += __shfl_xor_sync(0xffffffffu, rs0, 1);
    rs0 += __shfl_xor_sync(0xffffffffu, rs0, 2);
    rs1 += __shfl_xor_sync(0xffffffffu, rs1, 1);
    rs1 += __shfl_xor_sync(0xffffffffu, rs1, 2);
    const float inv0 = 1.f / rs0;
    const float inv1 = 1.f / rs1;

    // ---- write O (normalized) ----
    {
        float* orow0 = outO + (size_t)(b * QQ + qb0 + rloc) * EMBED + h * DH;
        float* orow1 = outO + (size_t)(b * QQ + qb0 + rloc + 8) * EMBED + h * DH;
#pragma unroll
        for (int nt = 0; nt < 16; nt++) {
            int col = nt * 8 + 2 * lq;
            *(float2*)(orow0 + col) = make_float2(oac[nt][0] * inv0, oac[nt][1] * inv0);
            *(float2*)(orow1 + col) = make_float2(oac[nt][2] * inv1, oac[nt][3] * inv1);
        }
    }

    // ---- tail: rescale this warp's weight rows in place (L2-hot) ----
    {
        float* wr0 = wbase + (size_t)rloc * KK;
        float* wr1 = wbase + (size_t)(rloc + 8) * KK;
#pragma unroll 4
        for (int c4 = lq * 4; c4 < KK; c4 += 16) {
            float4 w0 = *(float4*)(wr0 + c4);
            w0.x *= inv0; w0.y *= inv0; w0.z *= inv0; w0.w *= inv0;
            *(float4*)(wr0 + c4) = w0;
            float4 w1 = *(float4*)(wr1 + c4);
            w1.x *= inv1; w1.y *= inv1; w1.z *= inv1; w1.w *= inv1;
            *(float4*)(wr1 + c4) = w1;
        }
    }
}

// ---------------- launch ----------------
extern "C" void kernel_launch(void* const* d_in, const int* in_sizes, int n_in,
                              void* d_out, int out_size) {
    const float* query = (const float*)d_in[0];
    const float* key   = (const float*)d_in[1];
    const float* value = (const float*)d_in[2];
    const float* amask = (const float*)d_in[3];
    const float* qW = (const float*)d_in[4];
    const float* qb = (const float*)d_in[5];
    const float* kW = (const float*)d_in[6];
    const float* kb = (const float*)d_in[7];
    const float* vW = (const float*)d_in[8];
    const float* vb = (const float*)d_in[9];
    (void)in_sizes; (void)n_in; (void)out_size;

    float* outO = (float*)d_out;                             // [B,Q,EMBED]
    float* outW = outO + (size_t)BB * QQ * EMBED;            // [B,H,Q,K]

    __half *iqh, *iql, *ikh, *ikl, *wq, *wk;
    __half *fv, *fwv, *pvf;
    __half *pqh, *pql, *pkf;
    cudaGetSymbolAddress((void**)&iqh, i_qh); cudaGetSymbolAddress((void**)&iql, i_ql);
    cudaGetSymbolAddress((void**)&ikh, i_kh); cudaGetSymbolAddress((void**)&ikl, i_kl);
    cudaGetSymbolAddress((void**)&wq, wq16);  cudaGetSymbolAddress((void**)&wk, wk16);
    cudaGetSymbolAddress((void**)&fv, f_v);   cudaGetSymbolAddress((void**)&fwv, f_wv);
    cudaGetSymbolAddress((void**)&pvf, p_vf);
    cudaGetSymbolAddress((void**)&pqh, q16h); cudaGetSymbolAddress((void**)&pql, q16l);
    cudaGetSymbolAddress((void**)&pkf, k16);

    // 1. splits / converts (all fp16)
    {
        int n;
        n = BB * QQ * DOWN / 4;   split_fp16<<<(n + 255) / 256, 256>>>(query, iqh, iql, n);
        n = BB * KK * DOWN / 4;   split_fp16<<<(n + 255) / 256, 256>>>(key,   ikh, ikl, n);
        n = DOWN * DOWN / 4;      conv_fp16<<<(n + 255) / 256, 256>>>(qW, wq, n);
        n = DOWN * DOWN / 4;      conv_fp16<<<(n + 255) / 256, 256>>>(kW, wk, n);
        n = BB * KK * EMBED / 4;  conv_fp16<<<(n + 255) / 256, 256>>>(value, fv, n);
        n = EMBED * EMBED / 4;    conv_fp16<<<(n + 255) / 256, 256>>>(vW, fwv, n);
    }

    // 2. projection GEMMs (all fp16)
    {
        cudaFuncSetAttribute(gemm_mma_q<0>,
                             cudaFuncAttributeMaxDynamicSharedMemorySize, GQ_BYTES);
        cudaFuncSetAttribute(gemm_mma_q<1>,
                             cudaFuncAttributeMaxDynamicSharedMemorySize, GQ_BYTES);
        cudaFuncSetAttribute(gemm_mma_h1,
                             cudaFuncAttributeMaxDynamicSharedMemorySize, GH_BYTES);
        dim3 gq(DOWN / 128, (BB * QQ) / 128);
        gemm_mma_q<0><<<gq, 256, GQ_BYTES>>>(iqh, iql, wq, qb, pqh, pql,
                                             BB * QQ, DOWN, DOWN);
        gemm_mma_q<1><<<gq, 256, GQ_BYTES>>>(ikh, ikl, wk, kb, pkf, nullptr,
                                             BB * KK, DOWN, DOWN);
        dim3 gv(EMBED / 128, (BB * KK) / 128);
        gemm_mma_h1<<<gv, 256, GH_BYTES>>>(fv, fwv, vb, pvf,
                                           BB * KK, EMBED, EMBED);
    }

    // 3. attention (fp16 S 2-prod, PV 1-prod, fused per-group exp+PV)
    {
        cudaFuncSetAttribute(attn_mma,
                             cudaFuncAttributeMaxDynamicSharedMemorySize, A_BYTES);
        dim3 ga(QQ / 128, HH, BB);
        attn_mma<<<ga, 256, A_BYTES>>>(pqh, pql, pkf, pvf,
                                       amask, outO, outW);
    }
}